// round 2
// baseline (speedup 1.0000x reference)
#include <cuda_runtime.h>
#include <math.h>

#define HID 2048
#define NTOK 4096
#define HEADS 16
#define HDIM 128

// ---- scratch (static device arrays; no allocations allowed) ----
__device__ float g_Q[NTOK * HID];
__device__ float g_K[NTOK * HID];
__device__ float g_V[NTOK * HID];
__device__ float g_AO[NTOK * HID];

// =====================================================================
// SGEMM with bias: C[M,N] = A[M,K] @ B[K,N] + bias[N]
// 128x128x8 tiles, 256 threads, 8x8 per thread, double-buffered smem.
// =====================================================================
__global__ __launch_bounds__(256)
void sgemm_bias(const float* __restrict__ A, const float* __restrict__ B,
                const float* __restrict__ bias, float* __restrict__ C,
                int M, int N, int K)
{
    __shared__ float As[2][8][128];   // transposed: As[k][m]
    __shared__ float Bs[2][8][128];   // Bs[k][n]

    const int tid = threadIdx.x;
    const int tx = tid & 15;          // col-thread  0..15
    const int ty = tid >> 4;          // row-thread  0..15
    const int row0 = blockIdx.y * 128;
    const int col0 = blockIdx.x * 128;

    // A-tile load mapping: 128 rows x 8 cols, 1 float4 per thread
    const int ar = tid >> 1;          // 0..127
    const int ac = (tid & 1) * 4;     // 0 or 4
    // B-tile load mapping: 8 rows x 128 cols, 1 float4 per thread
    const int br = tid >> 5;          // 0..7
    const int bc = (tid & 31) * 4;    // 0..124

    const float* Aptr = A + (size_t)(row0 + ar) * K + ac;
    const float* Bptr = B + (size_t)br * N + col0 + bc;

    float acc[8][8];
    #pragma unroll
    for (int i = 0; i < 8; i++)
        #pragma unroll
        for (int j = 0; j < 8; j++) acc[i][j] = 0.f;

    // preload tile 0
    float4 a4 = *(const float4*)(Aptr);
    float4 b4 = *(const float4*)(Bptr);
    As[0][ac + 0][ar] = a4.x; As[0][ac + 1][ar] = a4.y;
    As[0][ac + 2][ar] = a4.z; As[0][ac + 3][ar] = a4.w;
    *(float4*)&Bs[0][br][bc] = b4;
    __syncthreads();

    const int nk = K >> 3;
    int buf = 0;
    for (int kt = 0; kt < nk; kt++) {
        if (kt + 1 < nk) {
            a4 = *(const float4*)(Aptr + (kt + 1) * 8);
            b4 = *(const float4*)(Bptr + (size_t)(kt + 1) * 8 * N);
        }
        #pragma unroll
        for (int k = 0; k < 8; k++) {
            float ra[8], rb[8];
            *(float4*)&ra[0] = *(float4*)&As[buf][k][ty * 4];
            *(float4*)&ra[4] = *(float4*)&As[buf][k][64 + ty * 4];
            *(float4*)&rb[0] = *(float4*)&Bs[buf][k][tx * 4];
            *(float4*)&rb[4] = *(float4*)&Bs[buf][k][64 + tx * 4];
            #pragma unroll
            for (int i = 0; i < 8; i++)
                #pragma unroll
                for (int j = 0; j < 8; j++)
                    acc[i][j] += ra[i] * rb[j];
        }
        if (kt + 1 < nk) {
            buf ^= 1;
            As[buf][ac + 0][ar] = a4.x; As[buf][ac + 1][ar] = a4.y;
            As[buf][ac + 2][ar] = a4.z; As[buf][ac + 3][ar] = a4.w;
            *(float4*)&Bs[buf][br][bc] = b4;
            __syncthreads();
        }
    }

    // epilogue: add bias, store (2 float4 per row)
    float blo[4], bhi[4];
    #pragma unroll
    for (int j = 0; j < 4; j++) {
        blo[j] = bias[col0 + tx * 4 + j];
        bhi[j] = bias[col0 + 64 + tx * 4 + j];
    }
    #pragma unroll
    for (int i = 0; i < 8; i++) {
        int row = row0 + ((i < 4) ? (ty * 4 + i) : (64 + ty * 4 + i - 4));
        float4 o0, o1;
        o0.x = acc[i][0] + blo[0]; o0.y = acc[i][1] + blo[1];
        o0.z = acc[i][2] + blo[2]; o0.w = acc[i][3] + blo[3];
        o1.x = acc[i][4] + bhi[0]; o1.y = acc[i][5] + bhi[1];
        o1.z = acc[i][6] + bhi[2]; o1.w = acc[i][7] + bhi[3];
        *(float4*)(C + (size_t)row * N + col0 + tx * 4) = o0;
        *(float4*)(C + (size_t)row * N + col0 + 64 + tx * 4) = o1;
    }
}

// =====================================================================
// Per-head LayerNorm over head_dim=128 for Q and K (in place).
// grid = NTOK tokens, block = 512 (16 warps, one warp per head).
// =====================================================================
__device__ __forceinline__ void ln_head(float* p, const float* g,
                                        const float* be, int lane)
{
    float4 x = *(float4*)(p + lane * 4);
    float s  = x.x + x.y + x.z + x.w;
    float ss = x.x * x.x + x.y * x.y + x.z * x.z + x.w * x.w;
    #pragma unroll
    for (int off = 16; off > 0; off >>= 1) {
        s  += __shfl_xor_sync(0xffffffffu, s,  off);
        ss += __shfl_xor_sync(0xffffffffu, ss, off);
    }
    float mean = s * (1.f / 128.f);
    float var  = ss * (1.f / 128.f) - mean * mean;
    float rstd = rsqrtf(var + 1e-6f);
    float4 gg = *(const float4*)(g  + lane * 4);
    float4 bb = *(const float4*)(be + lane * 4);
    x.x = (x.x - mean) * rstd * gg.x + bb.x;
    x.y = (x.y - mean) * rstd * gg.y + bb.y;
    x.z = (x.z - mean) * rstd * gg.z + bb.z;
    x.w = (x.w - mean) * rstd * gg.w + bb.w;
    *(float4*)(p + lane * 4) = x;
}

__global__ __launch_bounds__(512)
void qk_ln(float* __restrict__ Q, float* __restrict__ K,
           const float* __restrict__ qg, const float* __restrict__ qb,
           const float* __restrict__ kg, const float* __restrict__ kb)
{
    int t = blockIdx.x;
    int h = threadIdx.x >> 5;
    int lane = threadIdx.x & 31;
    ln_head(Q + (size_t)t * HID + h * HDIM, qg, qb, lane);
    ln_head(K + (size_t)t * HID + h * HDIM, kg, kb, lane);
}

// =====================================================================
// SIMT flash attention. One block = one (b,h) and one 64-row Q tile.
// 256 threads = 16 (ct) x 16 (rg). Thread owns S rows rg*4+r,
// S cols ct+16c; O cols ct*8..ct*8+7. P staged through smem.
// =====================================================================
#define QPAD 132                          // row stride (floats) for Q/K/V tiles
#define PPAD 65                           // row stride for P tile
#define FLASH_SMEM ((3 * 64 * QPAD + 64 * PPAD) * 4)

__global__ __launch_bounds__(256)
void flash_attn(const float* __restrict__ Qg, const float* __restrict__ Kg,
                const float* __restrict__ Vg, float* __restrict__ Og)
{
    extern __shared__ float sm[];
    float* Qs = sm;                    // 64 x QPAD
    float* Ks = Qs + 64 * QPAD;
    float* Vs = Ks + 64 * QPAD;
    float* Ps = Vs + 64 * QPAD;        // 64 x PPAD

    const int tid = threadIdx.x;
    const int ct = tid & 15;
    const int rg = tid >> 4;
    const int bh = blockIdx.y;
    const int b  = bh >> 4, h = bh & 15;
    const int q0 = blockIdx.x * 64;
    const size_t base = (size_t)b * 2048 * HID + (size_t)h * HDIM;
    const float scale = 0.08838834764831845f;   // 1/sqrt(128)

    // load Q tile (coalesced float4)
    for (int i = tid; i < 64 * 32; i += 256) {
        int r = i >> 5, c4 = (i & 31) << 2;
        *(float4*)(Qs + r * QPAD + c4) =
            *(const float4*)(Qg + base + (size_t)(q0 + r) * HID + c4);
    }

    float m_i[4], l_i[4], o[4][8];
    #pragma unroll
    for (int r = 0; r < 4; r++) {
        m_i[r] = -1e30f; l_i[r] = 0.f;
        #pragma unroll
        for (int c = 0; c < 8; c++) o[r][c] = 0.f;
    }

    for (int kt = 0; kt < 2048 / 64; kt++) {
        const int k0 = kt * 64;
        __syncthreads();                       // protect Ks/Vs/Ps reuse
        for (int i = tid; i < 64 * 32; i += 256) {
            int r = i >> 5, c4 = (i & 31) << 2;
            *(float4*)(Ks + r * QPAD + c4) =
                *(const float4*)(Kg + base + (size_t)(k0 + r) * HID + c4);
            *(float4*)(Vs + r * QPAD + c4) =
                *(const float4*)(Vg + base + (size_t)(k0 + r) * HID + c4);
        }
        __syncthreads();

        // ---- S = Q K^T (64x64x128), cols j = ct + 16c ----
        float s[4][4];
        #pragma unroll
        for (int r = 0; r < 4; r++)
            #pragma unroll
            for (int c = 0; c < 4; c++) s[r][c] = 0.f;

        #pragma unroll 8
        for (int k4 = 0; k4 < 32; k4++) {
            float4 qv[4], kv[4];
            #pragma unroll
            for (int r = 0; r < 4; r++)
                qv[r] = *(float4*)(Qs + (rg * 4 + r) * QPAD + k4 * 4);
            #pragma unroll
            for (int c = 0; c < 4; c++)
                kv[c] = *(float4*)(Ks + (ct + 16 * c) * QPAD + k4 * 4);
            #pragma unroll
            for (int r = 0; r < 4; r++)
                #pragma unroll
                for (int c = 0; c < 4; c++)
                    s[r][c] += qv[r].x * kv[c].x + qv[r].y * kv[c].y
                             + qv[r].z * kv[c].z + qv[r].w * kv[c].w;
        }

        // ---- online softmax ----
        float corr[4];
        #pragma unroll
        for (int r = 0; r < 4; r++) {
            float mx = fmaxf(fmaxf(s[r][0], s[r][1]), fmaxf(s[r][2], s[r][3]));
            #pragma unroll
            for (int off = 1; off < 16; off <<= 1)
                mx = fmaxf(mx, __shfl_xor_sync(0xffffffffu, mx, off));
            float mnew = fmaxf(m_i[r], mx * scale);
            corr[r] = __expf(m_i[r] - mnew);
            m_i[r] = mnew;
            l_i[r] *= corr[r];
        }
        #pragma unroll
        for (int r = 0; r < 4; r++)
            #pragma unroll
            for (int c = 0; c < 8; c++) o[r][c] *= corr[r];

        #pragma unroll
        for (int r = 0; r < 4; r++) {
            float ls = 0.f;
            #pragma unroll
            for (int c = 0; c < 4; c++) {
                float p = __expf(s[r][c] * scale - m_i[r]);
                Ps[(rg * 4 + r) * PPAD + ct + 16 * c] = p;
                ls += p;
            }
            #pragma unroll
            for (int off = 1; off < 16; off <<= 1)
                ls += __shfl_xor_sync(0xffffffffu, ls, off);
            l_i[r] += ls;
        }
        __syncthreads();                      // Ps complete

        // ---- O += P V (64x128x64), O cols ct*8.. ----
        #pragma unroll 4
        for (int j = 0; j < 64; j++) {
            float pr[4];
            #pragma unroll
            for (int r = 0; r < 4; r++)
                pr[r] = Ps[(rg * 4 + r) * PPAD + j];
            float4 v0 = *(float4*)(Vs + j * QPAD + ct * 8);
            float4 v1 = *(float4*)(Vs + j * QPAD + ct * 8 + 4);
            #pragma unroll
            for (int r = 0; r < 4; r++) {
                o[r][0] += pr[r] * v0.x; o[r][1] += pr[r] * v0.y;
                o[r][2] += pr[r] * v0.z; o[r][3] += pr[r] * v0.w;
                o[r][4] += pr[r] * v1.x; o[r][5] += pr[r] * v1.y;
                o[r][6] += pr[r] * v1.z; o[r][7] += pr[r] * v1.w;
            }
        }
    }

    // ---- final normalize + store ----
    #pragma unroll
    for (int r = 0; r < 4; r++) {
        float inv = 1.f / l_i[r];
        float4 o0, o1;
        o0.x = o[r][0] * inv; o0.y = o[r][1] * inv;
        o0.z = o[r][2] * inv; o0.w = o[r][3] * inv;
        o1.x = o[r][4] * inv; o1.y = o[r][5] * inv;
        o1.z = o[r][6] * inv; o1.w = o[r][7] * inv;
        size_t off = base + (size_t)(q0 + rg * 4 + r) * HID + ct * 8;
        *(float4*)(Og + off)     = o0;
        *(float4*)(Og + off + 4) = o1;
    }
}

// =====================================================================
// launcher
// =====================================================================
extern "C" void kernel_launch(void* const* d_in, const int* in_sizes, int n_in,
                              void* d_out, int out_size)
{
    const float* X   = (const float*)d_in[0];
    const float* qw  = (const float*)d_in[1];
    const float* qb  = (const float*)d_in[2];
    const float* kw  = (const float*)d_in[3];
    const float* kb  = (const float*)d_in[4];
    const float* vw  = (const float*)d_in[5];
    const float* vb  = (const float*)d_in[6];
    const float* ow  = (const float*)d_in[7];
    const float* ob  = (const float*)d_in[8];
    const float* qg  = (const float*)d_in[9];
    const float* qnb = (const float*)d_in[10];
    const float* kg  = (const float*)d_in[11];
    const float* knb = (const float*)d_in[12];
    float* out = (float*)d_out;

    float *Q, *K, *V, *AO;
    cudaGetSymbolAddress((void**)&Q,  g_Q);
    cudaGetSymbolAddress((void**)&K,  g_K);
    cudaGetSymbolAddress((void**)&V,  g_V);
    cudaGetSymbolAddress((void**)&AO, g_AO);

    cudaFuncSetAttribute(flash_attn,
                         cudaFuncAttributeMaxDynamicSharedMemorySize,
                         FLASH_SMEM);

    dim3 gg(HID / 128, NTOK / 128);   // (16, 32)
    dim3 bb(256);
    sgemm_bias<<<gg, bb>>>(X, qw, qb, Q, NTOK, HID, HID);
    sgemm_bias<<<gg, bb>>>(X, kw, kb, K, NTOK, HID, HID);
    sgemm_bias<<<gg, bb>>>(X, vw, vb, V, NTOK, HID, HID);

    qk_ln<<<NTOK, 512>>>(Q, K, qg, qnb, kg, knb);

    flash_attn<<<dim3(2048 / 64, 32), 256, FLASH_SMEM>>>(Q, K, V, AO);

    sgemm_bias<<<gg, bb>>>(AO, ow, ob, out, NTOK, HID, HID);
}

// round 3
// speedup vs baseline: 1.5185x; 1.5185x over previous
#include <cuda_runtime.h>
#include <math.h>

#define HID 2048
#define NTOK 4096
#define HEADS 16
#define HDIM 128

// ---- scratch (static device arrays; no allocations allowed) ----
__device__ float g_Q[NTOK * HID];
__device__ float g_K[NTOK * HID];
__device__ float g_V[NTOK * HID];
__device__ float g_AO[NTOK * HID];

// =====================================================================
// TF32 tensor-core GEMM with bias: C[M,N] = A[M,K] @ B[K,N] + bias[N]
// 128x128x16 block tile, 256 threads (8 warps, 4x2), warp tile 32x64,
// mma.m16n8k8.tf32, cp.async double-buffered smem.
// Smem strides chosen for conflict-free fragment LDS:
//   As [128 rows][stride 20]  (bank = (20m+k) mod 32 -> 32 distinct)
//   Bs [16 rows ][stride 136] (bank = (8k+n)  mod 32 -> 32 distinct)
// =====================================================================
#define ASTRIDE 20
#define BSTRIDE 136

__device__ __forceinline__ unsigned f2tf32(float f) {
    unsigned u;
    asm("cvt.rna.tf32.f32 %0, %1;" : "=r"(u) : "f"(f));
    return u;
}

__device__ __forceinline__ void cp_async16(void* smem_dst, const void* gptr) {
    unsigned saddr = (unsigned)__cvta_generic_to_shared(smem_dst);
    asm volatile("cp.async.cg.shared.global [%0], [%1], 16;\n"
                 :: "r"(saddr), "l"(gptr));
}
__device__ __forceinline__ void cp_commit() {
    asm volatile("cp.async.commit_group;\n");
}
__device__ __forceinline__ void cp_wait1() {
    asm volatile("cp.async.wait_group 1;\n");
}
__device__ __forceinline__ void cp_wait0() {
    asm volatile("cp.async.wait_group 0;\n");
}

__global__ __launch_bounds__(256)
void tf32_gemm_bias(const float* __restrict__ A, const float* __restrict__ B,
                    const float* __restrict__ bias, float* __restrict__ C,
                    int M, int N, int K)
{
    __shared__ float As[2][128 * ASTRIDE];
    __shared__ float Bs[2][16 * BSTRIDE];

    const int tid  = threadIdx.x;
    const int lane = tid & 31;
    const int wid  = tid >> 5;
    const int warpM = wid & 3;        // 0..3 -> 32 rows each
    const int warpN = wid >> 2;       // 0..1 -> 64 cols each
    const int row0 = blockIdx.y * 128;
    const int col0 = blockIdx.x * 128;

    // A tile loads: 128 rows x 16 k = 512 float4; thread handles i=tid, tid+256
    // i -> row = i>>2, k4 = (i&3)*4
    // B tile loads: 16 rows x 128 n = 512 float4; i -> krow = i>>5, n4 = (i&31)*4
    const int a_r0 = tid >> 2,      a_k = (tid & 3) * 4;
    const int b_k0 = tid >> 5,      b_n = (tid & 31) * 4;

    float acc[2][8][4];
    #pragma unroll
    for (int i = 0; i < 2; i++)
        #pragma unroll
        for (int j = 0; j < 8; j++)
            #pragma unroll
            for (int c = 0; c < 4; c++) acc[i][j][c] = 0.f;

    const int nk = K >> 4;            // 16 per tile

    // ---- prologue: issue tile 0 ----
    {
        const float* ag = A + (size_t)(row0 + a_r0) * K + a_k;
        cp_async16(&As[0][a_r0 * ASTRIDE + a_k], ag);
        cp_async16(&As[0][(a_r0 + 64) * ASTRIDE + a_k], ag + (size_t)64 * K);
        const float* bg = B + (size_t)b_k0 * N + col0 + b_n;
        cp_async16(&Bs[0][b_k0 * BSTRIDE + b_n], bg);
        cp_async16(&Bs[0][(b_k0 + 8) * BSTRIDE + b_n], bg + (size_t)8 * N);
        cp_commit();
    }

    int buf = 0;
    for (int kt = 0; kt < nk; kt++) {
        if (kt + 1 < nk) {
            const float* ag = A + (size_t)(row0 + a_r0) * K + (kt + 1) * 16 + a_k;
            cp_async16(&As[buf ^ 1][a_r0 * ASTRIDE + a_k], ag);
            cp_async16(&As[buf ^ 1][(a_r0 + 64) * ASTRIDE + a_k], ag + (size_t)64 * K);
            const float* bg = B + (size_t)((kt + 1) * 16 + b_k0) * N + col0 + b_n;
            cp_async16(&Bs[buf ^ 1][b_k0 * BSTRIDE + b_n], bg);
            cp_async16(&Bs[buf ^ 1][(b_k0 + 8) * BSTRIDE + b_n], bg + (size_t)8 * N);
            cp_commit();
            cp_wait1();
        } else {
            cp_wait0();
        }
        __syncthreads();

        const float* as = &As[buf][0];
        const float* bs = &Bs[buf][0];

        #pragma unroll
        for (int kk = 0; kk < 16; kk += 8) {
            // B fragments: 8 n-tiles x 2 regs
            unsigned bf[8][2];
            #pragma unroll
            for (int tn = 0; tn < 8; tn++) {
                int n = warpN * 64 + tn * 8 + (lane >> 2);
                bf[tn][0] = f2tf32(bs[(kk +     (lane & 3)) * BSTRIDE + n]);
                bf[tn][1] = f2tf32(bs[(kk + 4 + (lane & 3)) * BSTRIDE + n]);
            }
            // A fragments: 2 m-tiles x 4 regs
            unsigned af[2][4];
            #pragma unroll
            for (int tm = 0; tm < 2; tm++) {
                int m = warpM * 32 + tm * 16 + (lane >> 2);
                af[tm][0] = f2tf32(as[m * ASTRIDE + kk + (lane & 3)]);
                af[tm][1] = f2tf32(as[(m + 8) * ASTRIDE + kk + (lane & 3)]);
                af[tm][2] = f2tf32(as[m * ASTRIDE + kk + 4 + (lane & 3)]);
                af[tm][3] = f2tf32(as[(m + 8) * ASTRIDE + kk + 4 + (lane & 3)]);
            }
            #pragma unroll
            for (int tm = 0; tm < 2; tm++)
                #pragma unroll
                for (int tn = 0; tn < 8; tn++) {
                    float* c = acc[tm][tn];
                    asm volatile(
                        "mma.sync.aligned.m16n8k8.row.col.f32.tf32.tf32.f32 "
                        "{%0,%1,%2,%3}, {%4,%5,%6,%7}, {%8,%9}, {%0,%1,%2,%3};\n"
                        : "+f"(c[0]), "+f"(c[1]), "+f"(c[2]), "+f"(c[3])
                        : "r"(af[tm][0]), "r"(af[tm][1]),
                          "r"(af[tm][2]), "r"(af[tm][3]),
                          "r"(bf[tn][0]), "r"(bf[tn][1]));
                }
        }
        __syncthreads();
        buf ^= 1;
    }

    // ---- epilogue: bias + store ----
    #pragma unroll
    for (int tm = 0; tm < 2; tm++) {
        int mrow = row0 + warpM * 32 + tm * 16 + (lane >> 2);
        #pragma unroll
        for (int tn = 0; tn < 8; tn++) {
            int ncol = col0 + warpN * 64 + tn * 8 + (lane & 3) * 2;
            float b0 = bias[ncol], b1 = bias[ncol + 1];
            float2 v0 = make_float2(acc[tm][tn][0] + b0, acc[tm][tn][1] + b1);
            float2 v1 = make_float2(acc[tm][tn][2] + b0, acc[tm][tn][3] + b1);
            *(float2*)(C + (size_t)mrow * N + ncol) = v0;
            *(float2*)(C + (size_t)(mrow + 8) * N + ncol) = v1;
        }
    }
}

// =====================================================================
// Per-head LayerNorm over head_dim=128 for Q and K (in place).
// =====================================================================
__device__ __forceinline__ void ln_head(float* p, const float* g,
                                        const float* be, int lane)
{
    float4 x = *(float4*)(p + lane * 4);
    float s  = x.x + x.y + x.z + x.w;
    float ss = x.x * x.x + x.y * x.y + x.z * x.z + x.w * x.w;
    #pragma unroll
    for (int off = 16; off > 0; off >>= 1) {
        s  += __shfl_xor_sync(0xffffffffu, s,  off);
        ss += __shfl_xor_sync(0xffffffffu, ss, off);
    }
    float mean = s * (1.f / 128.f);
    float var  = ss * (1.f / 128.f) - mean * mean;
    float rstd = rsqrtf(var + 1e-6f);
    float4 gg = *(const float4*)(g  + lane * 4);
    float4 bb = *(const float4*)(be + lane * 4);
    x.x = (x.x - mean) * rstd * gg.x + bb.x;
    x.y = (x.y - mean) * rstd * gg.y + bb.y;
    x.z = (x.z - mean) * rstd * gg.z + bb.z;
    x.w = (x.w - mean) * rstd * gg.w + bb.w;
    *(float4*)(p + lane * 4) = x;
}

__global__ __launch_bounds__(512)
void qk_ln(float* __restrict__ Q, float* __restrict__ K,
           const float* __restrict__ qg, const float* __restrict__ qb,
           const float* __restrict__ kg, const float* __restrict__ kb)
{
    int t = blockIdx.x;
    int h = threadIdx.x >> 5;
    int lane = threadIdx.x & 31;
    ln_head(Q + (size_t)t * HID + h * HDIM, qg, qb, lane);
    ln_head(K + (size_t)t * HID + h * HDIM, kg, kb, lane);
}

// =====================================================================
// SIMT flash attention (fp32). One block = one (b,h) x 64-row Q tile.
// =====================================================================
#define QPAD 132
#define PPAD 65
#define FLASH_SMEM ((3 * 64 * QPAD + 64 * PPAD) * 4)

__global__ __launch_bounds__(256)
void flash_attn(const float* __restrict__ Qg, const float* __restrict__ Kg,
                const float* __restrict__ Vg, float* __restrict__ Og)
{
    extern __shared__ float sm[];
    float* Qs = sm;
    float* Ks = Qs + 64 * QPAD;
    float* Vs = Ks + 64 * QPAD;
    float* Ps = Vs + 64 * QPAD;

    const int tid = threadIdx.x;
    const int ct = tid & 15;
    const int rg = tid >> 4;
    const int bh = blockIdx.y;
    const int b  = bh >> 4, h = bh & 15;
    const int q0 = blockIdx.x * 64;
    const size_t base = (size_t)b * 2048 * HID + (size_t)h * HDIM;
    const float scale = 0.08838834764831845f;

    for (int i = tid; i < 64 * 32; i += 256) {
        int r = i >> 5, c4 = (i & 31) << 2;
        *(float4*)(Qs + r * QPAD + c4) =
            *(const float4*)(Qg + base + (size_t)(q0 + r) * HID + c4);
    }

    float m_i[4], l_i[4], o[4][8];
    #pragma unroll
    for (int r = 0; r < 4; r++) {
        m_i[r] = -1e30f; l_i[r] = 0.f;
        #pragma unroll
        for (int c = 0; c < 8; c++) o[r][c] = 0.f;
    }

    for (int kt = 0; kt < 2048 / 64; kt++) {
        const int k0 = kt * 64;
        __syncthreads();
        for (int i = tid; i < 64 * 32; i += 256) {
            int r = i >> 5, c4 = (i & 31) << 2;
            *(float4*)(Ks + r * QPAD + c4) =
                *(const float4*)(Kg + base + (size_t)(k0 + r) * HID + c4);
            *(float4*)(Vs + r * QPAD + c4) =
                *(const float4*)(Vg + base + (size_t)(k0 + r) * HID + c4);
        }
        __syncthreads();

        float s[4][4];
        #pragma unroll
        for (int r = 0; r < 4; r++)
            #pragma unroll
            for (int c = 0; c < 4; c++) s[r][c] = 0.f;

        #pragma unroll 8
        for (int k4 = 0; k4 < 32; k4++) {
            float4 qv[4], kv[4];
            #pragma unroll
            for (int r = 0; r < 4; r++)
                qv[r] = *(float4*)(Qs + (rg * 4 + r) * QPAD + k4 * 4);
            #pragma unroll
            for (int c = 0; c < 4; c++)
                kv[c] = *(float4*)(Ks + (ct + 16 * c) * QPAD + k4 * 4);
            #pragma unroll
            for (int r = 0; r < 4; r++)
                #pragma unroll
                for (int c = 0; c < 4; c++)
                    s[r][c] += qv[r].x * kv[c].x + qv[r].y * kv[c].y
                             + qv[r].z * kv[c].z + qv[r].w * kv[c].w;
        }

        float corr[4];
        #pragma unroll
        for (int r = 0; r < 4; r++) {
            float mx = fmaxf(fmaxf(s[r][0], s[r][1]), fmaxf(s[r][2], s[r][3]));
            #pragma unroll
            for (int off = 1; off < 16; off <<= 1)
                mx = fmaxf(mx, __shfl_xor_sync(0xffffffffu, mx, off));
            float mnew = fmaxf(m_i[r], mx * scale);
            corr[r] = __expf(m_i[r] - mnew);
            m_i[r] = mnew;
            l_i[r] *= corr[r];
        }
        #pragma unroll
        for (int r = 0; r < 4; r++)
            #pragma unroll
            for (int c = 0; c < 8; c++) o[r][c] *= corr[r];

        #pragma unroll
        for (int r = 0; r < 4; r++) {
            float ls = 0.f;
            #pragma unroll
            for (int c = 0; c < 4; c++) {
                float p = __expf(s[r][c] * scale - m_i[r]);
                Ps[(rg * 4 + r) * PPAD + ct + 16 * c] = p;
                ls += p;
            }
            #pragma unroll
            for (int off = 1; off < 16; off <<= 1)
                ls += __shfl_xor_sync(0xffffffffu, ls, off);
            l_i[r] += ls;
        }
        __syncthreads();

        #pragma unroll 4
        for (int j = 0; j < 64; j++) {
            float pr[4];
            #pragma unroll
            for (int r = 0; r < 4; r++)
                pr[r] = Ps[(rg * 4 + r) * PPAD + j];
            float4 v0 = *(float4*)(Vs + j * QPAD + ct * 8);
            float4 v1 = *(float4*)(Vs + j * QPAD + ct * 8 + 4);
            #pragma unroll
            for (int r = 0; r < 4; r++) {
                o[r][0] += pr[r] * v0.x; o[r][1] += pr[r] * v0.y;
                o[r][2] += pr[r] * v0.z; o[r][3] += pr[r] * v0.w;
                o[r][4] += pr[r] * v1.x; o[r][5] += pr[r] * v1.y;
                o[r][6] += pr[r] * v1.z; o[r][7] += pr[r] * v1.w;
            }
        }
    }

    #pragma unroll
    for (int r = 0; r < 4; r++) {
        float inv = 1.f / l_i[r];
        float4 o0, o1;
        o0.x = o[r][0] * inv; o0.y = o[r][1] * inv;
        o0.z = o[r][2] * inv; o0.w = o[r][3] * inv;
        o1.x = o[r][4] * inv; o1.y = o[r][5] * inv;
        o1.z = o[r][6] * inv; o1.w = o[r][7] * inv;
        size_t off = base + (size_t)(q0 + rg * 4 + r) * HID + ct * 8;
        *(float4*)(Og + off)     = o0;
        *(float4*)(Og + off + 4) = o1;
    }
}

// =====================================================================
// launcher
// =====================================================================
extern "C" void kernel_launch(void* const* d_in, const int* in_sizes, int n_in,
                              void* d_out, int out_size)
{
    const float* X   = (const float*)d_in[0];
    const float* qw  = (const float*)d_in[1];
    const float* qb  = (const float*)d_in[2];
    const float* kw  = (const float*)d_in[3];
    const float* kb  = (const float*)d_in[4];
    const float* vw  = (const float*)d_in[5];
    const float* vb  = (const float*)d_in[6];
    const float* ow  = (const float*)d_in[7];
    const float* ob  = (const float*)d_in[8];
    const float* qg  = (const float*)d_in[9];
    const float* qnb = (const float*)d_in[10];
    const float* kg  = (const float*)d_in[11];
    const float* knb = (const float*)d_in[12];
    float* out = (float*)d_out;

    float *Q, *K, *V, *AO;
    cudaGetSymbolAddress((void**)&Q,  g_Q);
    cudaGetSymbolAddress((void**)&K,  g_K);
    cudaGetSymbolAddress((void**)&V,  g_V);
    cudaGetSymbolAddress((void**)&AO, g_AO);

    cudaFuncSetAttribute(flash_attn,
                         cudaFuncAttributeMaxDynamicSharedMemorySize,
                         FLASH_SMEM);

    dim3 gg(HID / 128, NTOK / 128);   // (16, 32)
    dim3 bb(256);
    tf32_gemm_bias<<<gg, bb>>>(X, qw, qb, Q, NTOK, HID, HID);
    tf32_gemm_bias<<<gg, bb>>>(X, kw, kb, K, NTOK, HID, HID);
    tf32_gemm_bias<<<gg, bb>>>(X, vw, vb, V, NTOK, HID, HID);

    qk_ln<<<NTOK, 512>>>(Q, K, qg, qnb, kg, knb);

    flash_attn<<<dim3(2048 / 64, 32), 256, FLASH_SMEM>>>(Q, K, V, AO);

    tf32_gemm_bias<<<gg, bb>>>(AO, ow, ob, out, NTOK, HID, HID);
}

// round 4
// speedup vs baseline: 3.0065x; 1.9799x over previous
#include <cuda_runtime.h>
#include <math.h>

#define HID 2048
#define NTOK 4096
#define HEADS 16
#define HDIM 128

// ---- scratch (static device arrays; no allocations allowed) ----
__device__ float g_Q[NTOK * HID];
__device__ float g_K[NTOK * HID];
__device__ float g_V[NTOK * HID];
__device__ float g_AO[NTOK * HID];

// =====================================================================
// helpers
// =====================================================================
__device__ __forceinline__ unsigned f2tf32(float f) {
    unsigned u;
    asm("cvt.rna.tf32.f32 %0, %1;" : "=r"(u) : "f"(f));
    return u;
}
__device__ __forceinline__ void mma_tf32(float* c, const unsigned* a,
                                         const unsigned* b) {
    asm volatile(
        "mma.sync.aligned.m16n8k8.row.col.f32.tf32.tf32.f32 "
        "{%0,%1,%2,%3}, {%4,%5,%6,%7}, {%8,%9}, {%0,%1,%2,%3};\n"
        : "+f"(c[0]), "+f"(c[1]), "+f"(c[2]), "+f"(c[3])
        : "r"(a[0]), "r"(a[1]), "r"(a[2]), "r"(a[3]),
          "r"(b[0]), "r"(b[1]));
}
__device__ __forceinline__ void cp_async16(void* smem_dst, const void* gptr) {
    unsigned saddr = (unsigned)__cvta_generic_to_shared(smem_dst);
    asm volatile("cp.async.cg.shared.global [%0], [%1], 16;\n"
                 :: "r"(saddr), "l"(gptr));
}
__device__ __forceinline__ void cp_commit() {
    asm volatile("cp.async.commit_group;\n");
}
__device__ __forceinline__ void cp_wait1() {
    asm volatile("cp.async.wait_group 1;\n");
}
__device__ __forceinline__ void cp_wait0() {
    asm volatile("cp.async.wait_group 0;\n");
}

// =====================================================================
// TF32 tensor-core GEMM with bias: C[M,N] = A[M,K] @ B[K,N] + bias[N]
// 128x128x16 block tile, 128 threads (4 warps, 2x2), warp tile 64x64.
// Per kk-slice per block: 128 warp-LDS vs 128 HMMA (1:1 balance).
// =====================================================================
#define ASTRIDE 20
#define BSTRIDE 136

__global__ __launch_bounds__(128)
void tf32_gemm_bias(const float* __restrict__ A, const float* __restrict__ B,
                    const float* __restrict__ bias, float* __restrict__ C,
                    int M, int N, int K)
{
    __shared__ float As[2][128 * ASTRIDE];
    __shared__ float Bs[2][16 * BSTRIDE];

    const int tid  = threadIdx.x;
    const int lane = tid & 31;
    const int g    = lane >> 2;       // 0..7
    const int t    = lane & 3;        // 0..3
    const int wid  = tid >> 5;        // 0..3
    const int warpM = wid & 1;        // 2 x 64 rows
    const int warpN = wid >> 1;       // 2 x 64 cols
    const int row0 = blockIdx.y * 128;
    const int col0 = blockIdx.x * 128;

    // A tile: 128 rows x 16 k = 512 float4; 4 per thread (rows +32 apart)
    const int a_r = tid >> 2,  a_k = (tid & 3) * 4;
    // B tile: 16 rows x 128 n = 512 float4; 4 per thread (krows +4 apart)
    const int b_k = tid >> 5,  b_n = (tid & 31) * 4;

    float acc[4][8][4];
    #pragma unroll
    for (int i = 0; i < 4; i++)
        #pragma unroll
        for (int j = 0; j < 8; j++)
            #pragma unroll
            for (int c = 0; c < 4; c++) acc[i][j][c] = 0.f;

    const int nk = K >> 4;

    // prologue: tile 0
    {
        const float* ag = A + (size_t)(row0 + a_r) * K + a_k;
        #pragma unroll
        for (int r = 0; r < 4; r++)
            cp_async16(&As[0][(a_r + 32 * r) * ASTRIDE + a_k],
                       ag + (size_t)(32 * r) * K);
        const float* bg = B + (size_t)b_k * N + col0 + b_n;
        #pragma unroll
        for (int r = 0; r < 4; r++)
            cp_async16(&Bs[0][(b_k + 4 * r) * BSTRIDE + b_n],
                       bg + (size_t)(4 * r) * N);
        cp_commit();
    }

    int buf = 0;
    for (int kt = 0; kt < nk; kt++) {
        if (kt + 1 < nk) {
            const float* ag = A + (size_t)(row0 + a_r) * K + (kt + 1) * 16 + a_k;
            #pragma unroll
            for (int r = 0; r < 4; r++)
                cp_async16(&As[buf ^ 1][(a_r + 32 * r) * ASTRIDE + a_k],
                           ag + (size_t)(32 * r) * K);
            const float* bg = B + (size_t)((kt + 1) * 16 + b_k) * N + col0 + b_n;
            #pragma unroll
            for (int r = 0; r < 4; r++)
                cp_async16(&Bs[buf ^ 1][(b_k + 4 * r) * BSTRIDE + b_n],
                           bg + (size_t)(4 * r) * N);
            cp_commit();
            cp_wait1();
        } else {
            cp_wait0();
        }
        __syncthreads();

        const float* as = &As[buf][0];
        const float* bs = &Bs[buf][0];

        #pragma unroll
        for (int kk = 0; kk < 16; kk += 8) {
            unsigned bf[8][2];
            #pragma unroll
            for (int tn = 0; tn < 8; tn++) {
                int n = warpN * 64 + tn * 8 + g;
                bf[tn][0] = f2tf32(bs[(kk +     t) * BSTRIDE + n]);
                bf[tn][1] = f2tf32(bs[(kk + 4 + t) * BSTRIDE + n]);
            }
            unsigned af[4][4];
            #pragma unroll
            for (int tm = 0; tm < 4; tm++) {
                int m = warpM * 64 + tm * 16 + g;
                af[tm][0] = f2tf32(as[m * ASTRIDE + kk + t]);
                af[tm][1] = f2tf32(as[(m + 8) * ASTRIDE + kk + t]);
                af[tm][2] = f2tf32(as[m * ASTRIDE + kk + 4 + t]);
                af[tm][3] = f2tf32(as[(m + 8) * ASTRIDE + kk + 4 + t]);
            }
            #pragma unroll
            for (int tm = 0; tm < 4; tm++)
                #pragma unroll
                for (int tn = 0; tn < 8; tn++)
                    mma_tf32(acc[tm][tn], af[tm], bf[tn]);
        }
        __syncthreads();
        buf ^= 1;
    }

    // epilogue
    #pragma unroll
    for (int tm = 0; tm < 4; tm++) {
        int mrow = row0 + warpM * 64 + tm * 16 + g;
        #pragma unroll
        for (int tn = 0; tn < 8; tn++) {
            int ncol = col0 + warpN * 64 + tn * 8 + t * 2;
            float b0 = bias[ncol], b1 = bias[ncol + 1];
            float2 v0 = make_float2(acc[tm][tn][0] + b0, acc[tm][tn][1] + b1);
            float2 v1 = make_float2(acc[tm][tn][2] + b0, acc[tm][tn][3] + b1);
            *(float2*)(C + (size_t)mrow * N + ncol) = v0;
            *(float2*)(C + (size_t)(mrow + 8) * N + ncol) = v1;
        }
    }
}

// =====================================================================
// Per-head LayerNorm over head_dim=128 for Q and K (in place).
// =====================================================================
__device__ __forceinline__ void ln_head(float* p, const float* g,
                                        const float* be, int lane)
{
    float4 x = *(float4*)(p + lane * 4);
    float s  = x.x + x.y + x.z + x.w;
    float ss = x.x * x.x + x.y * x.y + x.z * x.z + x.w * x.w;
    #pragma unroll
    for (int off = 16; off > 0; off >>= 1) {
        s  += __shfl_xor_sync(0xffffffffu, s,  off);
        ss += __shfl_xor_sync(0xffffffffu, ss, off);
    }
    float mean = s * (1.f / 128.f);
    float var  = ss * (1.f / 128.f) - mean * mean;
    float rstd = rsqrtf(var + 1e-6f);
    float4 gg = *(const float4*)(g  + lane * 4);
    float4 bb = *(const float4*)(be + lane * 4);
    x.x = (x.x - mean) * rstd * gg.x + bb.x;
    x.y = (x.y - mean) * rstd * gg.y + bb.y;
    x.z = (x.z - mean) * rstd * gg.z + bb.z;
    x.w = (x.w - mean) * rstd * gg.w + bb.w;
    *(float4*)(p + lane * 4) = x;
}

__global__ __launch_bounds__(512)
void qk_ln(float* __restrict__ Q, float* __restrict__ K,
           const float* __restrict__ qg, const float* __restrict__ qb,
           const float* __restrict__ kg, const float* __restrict__ kb)
{
    int tk = blockIdx.x;
    int h = threadIdx.x >> 5;
    int lane = threadIdx.x & 31;
    ln_head(Q + (size_t)tk * HID + h * HDIM, qg, qb, lane);
    ln_head(K + (size_t)tk * HID + h * HDIM, kg, kb, lane);
}

// =====================================================================
// Tensor-core flash attention (tf32 mma).
// Block = one (b,h) x 128 Q rows. 256 threads = 8 warps; warp w owns
// Q rows w*16..w*16+15 (private online-softmax state, per-warp P smem).
// K/V tiles of 64 keys per iteration.
// Smem strides: Q/K 132 (bank 4g+t distinct), V 136 (bank 8t+g distinct),
// P 68 (read bank 4g+t distinct).
// =====================================================================
#define QSTR 132
#define KSTR 132
#define VSTR 136
#define PSTR 68
#define FLASH_SMEM ((128 * QSTR + 64 * KSTR + 64 * VSTR + 8 * 16 * PSTR) * 4)

__global__ __launch_bounds__(256)
void flash_attn_tc(const float* __restrict__ Qg, const float* __restrict__ Kg,
                   const float* __restrict__ Vg, float* __restrict__ Og)
{
    extern __shared__ float sm[];
    float* Qs = sm;                       // 128 x QSTR (pre-scaled)
    float* Ks = Qs + 128 * QSTR;          // 64 x KSTR
    float* Vs = Ks + 64 * KSTR;           // 64 x VSTR
    float* Pw = Vs + 64 * VSTR;           // 8 x (16 x PSTR)

    const int tid  = threadIdx.x;
    const int lane = tid & 31;
    const int w    = tid >> 5;            // warp 0..7
    const int g    = lane >> 2;           // 0..7
    const int t    = lane & 3;            // 0..3
    const int bh = blockIdx.y;
    const int b  = bh >> 4, h = bh & 15;
    const int q0 = blockIdx.x * 128;
    const size_t base = (size_t)b * 2048 * HID + (size_t)h * HDIM;
    const float scale = 0.08838834764831845f;   // 1/sqrt(128)

    float* Ps = Pw + w * 16 * PSTR;
    const int wrow = w * 16;              // warp's first Q row in tile

    // ---- load Q tile, pre-scaled ----
    for (int i = tid; i < 128 * 32; i += 256) {
        int r = i >> 5, c4 = (i & 31) << 2;
        float4 q = *(const float4*)(Qg + base + (size_t)(q0 + r) * HID + c4);
        q.x *= scale; q.y *= scale; q.z *= scale; q.w *= scale;
        *(float4*)(Qs + r * QSTR + c4) = q;
    }

    // online-softmax state: rows g (idx 0) and g+8 (idx 1)
    float m0 = -1e30f, m1 = -1e30f, l0 = 0.f, l1 = 0.f;
    float o[16][4];
    #pragma unroll
    for (int nt = 0; nt < 16; nt++)
        #pragma unroll
        for (int c = 0; c < 4; c++) o[nt][c] = 0.f;

    for (int kt = 0; kt < 2048 / 64; kt++) {
        const int k0 = kt * 64;
        __syncthreads();                  // prior PV reads of Ks/Vs done
        for (int i = tid; i < 64 * 32; i += 256) {
            int r = i >> 5, c4 = (i & 31) << 2;
            *(float4*)(Ks + r * KSTR + c4) =
                *(const float4*)(Kg + base + (size_t)(k0 + r) * HID + c4);
            *(float4*)(Vs + r * VSTR + c4) =
                *(const float4*)(Vg + base + (size_t)(k0 + r) * HID + c4);
        }
        __syncthreads();

        // ---- S = Q_tile(16) x K_tile(64)^T, k = 128 ----
        float s[8][4];
        #pragma unroll
        for (int nt = 0; nt < 8; nt++)
            #pragma unroll
            for (int c = 0; c < 4; c++) s[nt][c] = 0.f;

        #pragma unroll
        for (int kk = 0; kk < 128; kk += 8) {
            unsigned af[4];
            af[0] = f2tf32(Qs[(wrow + g) * QSTR + kk + t]);
            af[1] = f2tf32(Qs[(wrow + 8 + g) * QSTR + kk + t]);
            af[2] = f2tf32(Qs[(wrow + g) * QSTR + kk + 4 + t]);
            af[3] = f2tf32(Qs[(wrow + 8 + g) * QSTR + kk + 4 + t]);
            #pragma unroll
            for (int nt = 0; nt < 8; nt++) {
                unsigned bf[2];
                bf[0] = f2tf32(Ks[(nt * 8 + g) * KSTR + kk + t]);
                bf[1] = f2tf32(Ks[(nt * 8 + g) * KSTR + kk + 4 + t]);
                mma_tf32(s[nt], af, bf);
            }
        }

        // ---- online softmax (rows g and g+8 of this warp) ----
        float mx0 = -1e30f, mx1 = -1e30f;
        #pragma unroll
        for (int nt = 0; nt < 8; nt++) {
            mx0 = fmaxf(mx0, fmaxf(s[nt][0], s[nt][1]));
            mx1 = fmaxf(mx1, fmaxf(s[nt][2], s[nt][3]));
        }
        #pragma unroll
        for (int off = 1; off < 4; off <<= 1) {
            mx0 = fmaxf(mx0, __shfl_xor_sync(0xffffffffu, mx0, off));
            mx1 = fmaxf(mx1, __shfl_xor_sync(0xffffffffu, mx1, off));
        }
        float mn0 = fmaxf(m0, mx0), mn1 = fmaxf(m1, mx1);
        float c0 = __expf(m0 - mn0), c1 = __expf(m1 - mn1);
        m0 = mn0; m1 = mn1;

        float ls0 = 0.f, ls1 = 0.f;
        #pragma unroll
        for (int nt = 0; nt < 8; nt++) {
            float p00 = __expf(s[nt][0] - m0);
            float p01 = __expf(s[nt][1] - m0);
            float p10 = __expf(s[nt][2] - m1);
            float p11 = __expf(s[nt][3] - m1);
            ls0 += p00 + p01;
            ls1 += p10 + p11;
            *(float2*)(Ps + g * PSTR + nt * 8 + 2 * t)       = make_float2(p00, p01);
            *(float2*)(Ps + (g + 8) * PSTR + nt * 8 + 2 * t) = make_float2(p10, p11);
        }
        #pragma unroll
        for (int off = 1; off < 4; off <<= 1) {
            ls0 += __shfl_xor_sync(0xffffffffu, ls0, off);
            ls1 += __shfl_xor_sync(0xffffffffu, ls1, off);
        }
        l0 = l0 * c0 + ls0;
        l1 = l1 * c1 + ls1;
        #pragma unroll
        for (int nt = 0; nt < 16; nt++) {
            o[nt][0] *= c0; o[nt][1] *= c0;
            o[nt][2] *= c1; o[nt][3] *= c1;
        }
        __syncwarp();                      // P visible within warp

        // ---- O += P(16x64) x V(64x128) ----
        #pragma unroll
        for (int kk = 0; kk < 64; kk += 8) {
            unsigned pf[4];
            pf[0] = f2tf32(Ps[g * PSTR + kk + t]);
            pf[1] = f2tf32(Ps[(g + 8) * PSTR + kk + t]);
            pf[2] = f2tf32(Ps[g * PSTR + kk + 4 + t]);
            pf[3] = f2tf32(Ps[(g + 8) * PSTR + kk + 4 + t]);
            #pragma unroll
            for (int nt = 0; nt < 16; nt++) {
                unsigned bf[2];
                bf[0] = f2tf32(Vs[(kk + t) * VSTR + nt * 8 + g]);
                bf[1] = f2tf32(Vs[(kk + 4 + t) * VSTR + nt * 8 + g]);
                mma_tf32(o[nt], pf, bf);
            }
        }
        __syncwarp();                      // P reads done before next write
    }

    // ---- normalize + store ----
    float inv0 = 1.f / l0, inv1 = 1.f / l1;
    int r0 = q0 + wrow + g, r1 = q0 + wrow + 8 + g;
    #pragma unroll
    for (int nt = 0; nt < 16; nt++) {
        int d = nt * 8 + 2 * t;
        *(float2*)(Og + base + (size_t)r0 * HID + d) =
            make_float2(o[nt][0] * inv0, o[nt][1] * inv0);
        *(float2*)(Og + base + (size_t)r1 * HID + d) =
            make_float2(o[nt][2] * inv1, o[nt][3] * inv1);
    }
}

// =====================================================================
// launcher
// =====================================================================
extern "C" void kernel_launch(void* const* d_in, const int* in_sizes, int n_in,
                              void* d_out, int out_size)
{
    const float* X   = (const float*)d_in[0];
    const float* qw  = (const float*)d_in[1];
    const float* qb  = (const float*)d_in[2];
    const float* kw  = (const float*)d_in[3];
    const float* kb  = (const float*)d_in[4];
    const float* vw  = (const float*)d_in[5];
    const float* vb  = (const float*)d_in[6];
    const float* ow  = (const float*)d_in[7];
    const float* ob  = (const float*)d_in[8];
    const float* qg  = (const float*)d_in[9];
    const float* qnb = (const float*)d_in[10];
    const float* kg  = (const float*)d_in[11];
    const float* knb = (const float*)d_in[12];
    float* out = (float*)d_out;

    float *Q, *K, *V, *AO;
    cudaGetSymbolAddress((void**)&Q,  g_Q);
    cudaGetSymbolAddress((void**)&K,  g_K);
    cudaGetSymbolAddress((void**)&V,  g_V);
    cudaGetSymbolAddress((void**)&AO, g_AO);

    cudaFuncSetAttribute(flash_attn_tc,
                         cudaFuncAttributeMaxDynamicSharedMemorySize,
                         FLASH_SMEM);

    dim3 gg(HID / 128, NTOK / 128);   // (16, 32)
    dim3 bb(128);
    tf32_gemm_bias<<<gg, bb>>>(X, qw, qb, Q, NTOK, HID, HID);
    tf32_gemm_bias<<<gg, bb>>>(X, kw, kb, K, NTOK, HID, HID);
    tf32_gemm_bias<<<gg, bb>>>(X, vw, vb, V, NTOK, HID, HID);

    qk_ln<<<NTOK, 512>>>(Q, K, qg, qnb, kg, knb);

    flash_attn_tc<<<dim3(2048 / 128, 32), 256, FLASH_SMEM>>>(Q, K, V, AO);

    tf32_gemm_bias<<<gg, bb>>>(AO, ow, ob, out, NTOK, HID, HID);
}

// round 5
// speedup vs baseline: 3.0071x; 1.0002x over previous
#include <cuda_runtime.h>
#include <math.h>

#define HID 2048
#define NTOK 4096
#define HEADS 16
#define HDIM 128

// ---- scratch (static device arrays; no allocations allowed) ----
__device__ float g_Q[NTOK * HID];
__device__ float g_K[NTOK * HID];
__device__ float g_V[NTOK * HID];
__device__ float g_AO[NTOK * HID];

// =====================================================================
// helpers
// =====================================================================
__device__ __forceinline__ unsigned f2tf32(float f) {
    unsigned u;
    asm("cvt.rna.tf32.f32 %0, %1;" : "=r"(u) : "f"(f));
    return u;
}
__device__ __forceinline__ void mma_tf32(float* c, const unsigned* a,
                                         const unsigned* b) {
    asm volatile(
        "mma.sync.aligned.m16n8k8.row.col.f32.tf32.tf32.f32 "
        "{%0,%1,%2,%3}, {%4,%5,%6,%7}, {%8,%9}, {%0,%1,%2,%3};\n"
        : "+f"(c[0]), "+f"(c[1]), "+f"(c[2]), "+f"(c[3])
        : "r"(a[0]), "r"(a[1]), "r"(a[2]), "r"(a[3]),
          "r"(b[0]), "r"(b[1]));
}
__device__ __forceinline__ void cp_async16(void* smem_dst, const void* gptr) {
    unsigned saddr = (unsigned)__cvta_generic_to_shared(smem_dst);
    asm volatile("cp.async.cg.shared.global [%0], [%1], 16;\n"
                 :: "r"(saddr), "l"(gptr));
}
__device__ __forceinline__ void cp_commit() {
    asm volatile("cp.async.commit_group;\n");
}
__device__ __forceinline__ void cp_wait1() {
    asm volatile("cp.async.wait_group 1;\n");
}
__device__ __forceinline__ void cp_wait0() {
    asm volatile("cp.async.wait_group 0;\n");
}

// =====================================================================
// TF32 tensor-core GEMM with bias: C[M,N] = A[M,K] @ B[K,N] + bias[N]
// 128x128x16 block tile, 128 threads (4 warps, 2x2), warp tile 64x64.
// Per kk-slice per block: 128 warp-LDS vs 128 HMMA (1:1 balance).
// =====================================================================
#define ASTRIDE 20
#define BSTRIDE 136

__global__ __launch_bounds__(128)
void tf32_gemm_bias(const float* __restrict__ A, const float* __restrict__ B,
                    const float* __restrict__ bias, float* __restrict__ C,
                    int M, int N, int K)
{
    __shared__ float As[2][128 * ASTRIDE];
    __shared__ float Bs[2][16 * BSTRIDE];

    const int tid  = threadIdx.x;
    const int lane = tid & 31;
    const int g    = lane >> 2;       // 0..7
    const int t    = lane & 3;        // 0..3
    const int wid  = tid >> 5;        // 0..3
    const int warpM = wid & 1;        // 2 x 64 rows
    const int warpN = wid >> 1;       // 2 x 64 cols
    const int row0 = blockIdx.y * 128;
    const int col0 = blockIdx.x * 128;

    // A tile: 128 rows x 16 k = 512 float4; 4 per thread (rows +32 apart)
    const int a_r = tid >> 2,  a_k = (tid & 3) * 4;
    // B tile: 16 rows x 128 n = 512 float4; 4 per thread (krows +4 apart)
    const int b_k = tid >> 5,  b_n = (tid & 31) * 4;

    float acc[4][8][4];
    #pragma unroll
    for (int i = 0; i < 4; i++)
        #pragma unroll
        for (int j = 0; j < 8; j++)
            #pragma unroll
            for (int c = 0; c < 4; c++) acc[i][j][c] = 0.f;

    const int nk = K >> 4;

    // prologue: tile 0
    {
        const float* ag = A + (size_t)(row0 + a_r) * K + a_k;
        #pragma unroll
        for (int r = 0; r < 4; r++)
            cp_async16(&As[0][(a_r + 32 * r) * ASTRIDE + a_k],
                       ag + (size_t)(32 * r) * K);
        const float* bg = B + (size_t)b_k * N + col0 + b_n;
        #pragma unroll
        for (int r = 0; r < 4; r++)
            cp_async16(&Bs[0][(b_k + 4 * r) * BSTRIDE + b_n],
                       bg + (size_t)(4 * r) * N);
        cp_commit();
    }

    int buf = 0;
    for (int kt = 0; kt < nk; kt++) {
        if (kt + 1 < nk) {
            const float* ag = A + (size_t)(row0 + a_r) * K + (kt + 1) * 16 + a_k;
            #pragma unroll
            for (int r = 0; r < 4; r++)
                cp_async16(&As[buf ^ 1][(a_r + 32 * r) * ASTRIDE + a_k],
                           ag + (size_t)(32 * r) * K);
            const float* bg = B + (size_t)((kt + 1) * 16 + b_k) * N + col0 + b_n;
            #pragma unroll
            for (int r = 0; r < 4; r++)
                cp_async16(&Bs[buf ^ 1][(b_k + 4 * r) * BSTRIDE + b_n],
                           bg + (size_t)(4 * r) * N);
            cp_commit();
            cp_wait1();
        } else {
            cp_wait0();
        }
        __syncthreads();

        const float* as = &As[buf][0];
        const float* bs = &Bs[buf][0];

        #pragma unroll
        for (int kk = 0; kk < 16; kk += 8) {
            unsigned bf[8][2];
            #pragma unroll
            for (int tn = 0; tn < 8; tn++) {
                int n = warpN * 64 + tn * 8 + g;
                bf[tn][0] = f2tf32(bs[(kk +     t) * BSTRIDE + n]);
                bf[tn][1] = f2tf32(bs[(kk + 4 + t) * BSTRIDE + n]);
            }
            unsigned af[4][4];
            #pragma unroll
            for (int tm = 0; tm < 4; tm++) {
                int m = warpM * 64 + tm * 16 + g;
                af[tm][0] = f2tf32(as[m * ASTRIDE + kk + t]);
                af[tm][1] = f2tf32(as[(m + 8) * ASTRIDE + kk + t]);
                af[tm][2] = f2tf32(as[m * ASTRIDE + kk + 4 + t]);
                af[tm][3] = f2tf32(as[(m + 8) * ASTRIDE + kk + 4 + t]);
            }
            #pragma unroll
            for (int tm = 0; tm < 4; tm++)
                #pragma unroll
                for (int tn = 0; tn < 8; tn++)
                    mma_tf32(acc[tm][tn], af[tm], bf[tn]);
        }
        __syncthreads();
        buf ^= 1;
    }

    // epilogue
    #pragma unroll
    for (int tm = 0; tm < 4; tm++) {
        int mrow = row0 + warpM * 64 + tm * 16 + g;
        #pragma unroll
        for (int tn = 0; tn < 8; tn++) {
            int ncol = col0 + warpN * 64 + tn * 8 + t * 2;
            float b0 = bias[ncol], b1 = bias[ncol + 1];
            float2 v0 = make_float2(acc[tm][tn][0] + b0, acc[tm][tn][1] + b1);
            float2 v1 = make_float2(acc[tm][tn][2] + b0, acc[tm][tn][3] + b1);
            *(float2*)(C + (size_t)mrow * N + ncol) = v0;
            *(float2*)(C + (size_t)(mrow + 8) * N + ncol) = v1;
        }
    }
}

// =====================================================================
// Per-head LayerNorm over head_dim=128 for Q and K (in place).
// =====================================================================
__device__ __forceinline__ void ln_head(float* p, const float* g,
                                        const float* be, int lane)
{
    float4 x = *(float4*)(p + lane * 4);
    float s  = x.x + x.y + x.z + x.w;
    float ss = x.x * x.x + x.y * x.y + x.z * x.z + x.w * x.w;
    #pragma unroll
    for (int off = 16; off > 0; off >>= 1) {
        s  += __shfl_xor_sync(0xffffffffu, s,  off);
        ss += __shfl_xor_sync(0xffffffffu, ss, off);
    }
    float mean = s * (1.f / 128.f);
    float var  = ss * (1.f / 128.f) - mean * mean;
    float rstd = rsqrtf(var + 1e-6f);
    float4 gg = *(const float4*)(g  + lane * 4);
    float4 bb = *(const float4*)(be + lane * 4);
    x.x = (x.x - mean) * rstd * gg.x + bb.x;
    x.y = (x.y - mean) * rstd * gg.y + bb.y;
    x.z = (x.z - mean) * rstd * gg.z + bb.z;
    x.w = (x.w - mean) * rstd * gg.w + bb.w;
    *(float4*)(p + lane * 4) = x;
}

__global__ __launch_bounds__(512)
void qk_ln(float* __restrict__ Q, float* __restrict__ K,
           const float* __restrict__ qg, const float* __restrict__ qb,
           const float* __restrict__ kg, const float* __restrict__ kb)
{
    int tk = blockIdx.x;
    int h = threadIdx.x >> 5;
    int lane = threadIdx.x & 31;
    ln_head(Q + (size_t)tk * HID + h * HDIM, qg, qb, lane);
    ln_head(K + (size_t)tk * HID + h * HDIM, kg, kb, lane);
}

// =====================================================================
// Tensor-core flash attention (tf32 mma).
// Block = one (b,h) x 128 Q rows. 256 threads = 8 warps; warp w owns
// Q rows w*16..w*16+15 (private online-softmax state, per-warp P smem).
// K/V tiles of 64 keys per iteration.
// Smem strides: Q/K 132 (bank 4g+t distinct), V 136 (bank 8t+g distinct),
// P 68 (read bank 4g+t distinct).
// =====================================================================
#define QSTR 132
#define KSTR 132
#define VSTR 136
#define PSTR 68
#define FLASH_SMEM ((128 * QSTR + 64 * KSTR + 64 * VSTR + 8 * 16 * PSTR) * 4)

__global__ __launch_bounds__(256)
void flash_attn_tc(const float* __restrict__ Qg, const float* __restrict__ Kg,
                   const float* __restrict__ Vg, float* __restrict__ Og)
{
    extern __shared__ float sm[];
    float* Qs = sm;                       // 128 x QSTR (pre-scaled)
    float* Ks = Qs + 128 * QSTR;          // 64 x KSTR
    float* Vs = Ks + 64 * KSTR;           // 64 x VSTR
    float* Pw = Vs + 64 * VSTR;           // 8 x (16 x PSTR)

    const int tid  = threadIdx.x;
    const int lane = tid & 31;
    const int w    = tid >> 5;            // warp 0..7
    const int g    = lane >> 2;           // 0..7
    const int t    = lane & 3;            // 0..3
    const int bh = blockIdx.y;
    const int b  = bh >> 4, h = bh & 15;
    const int q0 = blockIdx.x * 128;
    const size_t base = (size_t)b * 2048 * HID + (size_t)h * HDIM;
    const float scale = 0.08838834764831845f;   // 1/sqrt(128)

    float* Ps = Pw + w * 16 * PSTR;
    const int wrow = w * 16;              // warp's first Q row in tile

    // ---- load Q tile, pre-scaled ----
    for (int i = tid; i < 128 * 32; i += 256) {
        int r = i >> 5, c4 = (i & 31) << 2;
        float4 q = *(const float4*)(Qg + base + (size_t)(q0 + r) * HID + c4);
        q.x *= scale; q.y *= scale; q.z *= scale; q.w *= scale;
        *(float4*)(Qs + r * QSTR + c4) = q;
    }

    // online-softmax state: rows g (idx 0) and g+8 (idx 1)
    float m0 = -1e30f, m1 = -1e30f, l0 = 0.f, l1 = 0.f;
    float o[16][4];
    #pragma unroll
    for (int nt = 0; nt < 16; nt++)
        #pragma unroll
        for (int c = 0; c < 4; c++) o[nt][c] = 0.f;

    for (int kt = 0; kt < 2048 / 64; kt++) {
        const int k0 = kt * 64;
        __syncthreads();                  // prior PV reads of Ks/Vs done
        for (int i = tid; i < 64 * 32; i += 256) {
            int r = i >> 5, c4 = (i & 31) << 2;
            *(float4*)(Ks + r * KSTR + c4) =
                *(const float4*)(Kg + base + (size_t)(k0 + r) * HID + c4);
            *(float4*)(Vs + r * VSTR + c4) =
                *(const float4*)(Vg + base + (size_t)(k0 + r) * HID + c4);
        }
        __syncthreads();

        // ---- S = Q_tile(16) x K_tile(64)^T, k = 128 ----
        float s[8][4];
        #pragma unroll
        for (int nt = 0; nt < 8; nt++)
            #pragma unroll
            for (int c = 0; c < 4; c++) s[nt][c] = 0.f;

        #pragma unroll
        for (int kk = 0; kk < 128; kk += 8) {
            unsigned af[4];
            af[0] = f2tf32(Qs[(wrow + g) * QSTR + kk + t]);
            af[1] = f2tf32(Qs[(wrow + 8 + g) * QSTR + kk + t]);
            af[2] = f2tf32(Qs[(wrow + g) * QSTR + kk + 4 + t]);
            af[3] = f2tf32(Qs[(wrow + 8 + g) * QSTR + kk + 4 + t]);
            #pragma unroll
            for (int nt = 0; nt < 8; nt++) {
                unsigned bf[2];
                bf[0] = f2tf32(Ks[(nt * 8 + g) * KSTR + kk + t]);
                bf[1] = f2tf32(Ks[(nt * 8 + g) * KSTR + kk + 4 + t]);
                mma_tf32(s[nt], af, bf);
            }
        }

        // ---- online softmax (rows g and g+8 of this warp) ----
        float mx0 = -1e30f, mx1 = -1e30f;
        #pragma unroll
        for (int nt = 0; nt < 8; nt++) {
            mx0 = fmaxf(mx0, fmaxf(s[nt][0], s[nt][1]));
            mx1 = fmaxf(mx1, fmaxf(s[nt][2], s[nt][3]));
        }
        #pragma unroll
        for (int off = 1; off < 4; off <<= 1) {
            mx0 = fmaxf(mx0, __shfl_xor_sync(0xffffffffu, mx0, off));
            mx1 = fmaxf(mx1, __shfl_xor_sync(0xffffffffu, mx1, off));
        }
        float mn0 = fmaxf(m0, mx0), mn1 = fmaxf(m1, mx1);
        float c0 = __expf(m0 - mn0), c1 = __expf(m1 - mn1);
        m0 = mn0; m1 = mn1;

        float ls0 = 0.f, ls1 = 0.f;
        #pragma unroll
        for (int nt = 0; nt < 8; nt++) {
            float p00 = __expf(s[nt][0] - m0);
            float p01 = __expf(s[nt][1] - m0);
            float p10 = __expf(s[nt][2] - m1);
            float p11 = __expf(s[nt][3] - m1);
            ls0 += p00 + p01;
            ls1 += p10 + p11;
            *(float2*)(Ps + g * PSTR + nt * 8 + 2 * t)       = make_float2(p00, p01);
            *(float2*)(Ps + (g + 8) * PSTR + nt * 8 + 2 * t) = make_float2(p10, p11);
        }
        #pragma unroll
        for (int off = 1; off < 4; off <<= 1) {
            ls0 += __shfl_xor_sync(0xffffffffu, ls0, off);
            ls1 += __shfl_xor_sync(0xffffffffu, ls1, off);
        }
        l0 = l0 * c0 + ls0;
        l1 = l1 * c1 + ls1;
        #pragma unroll
        for (int nt = 0; nt < 16; nt++) {
            o[nt][0] *= c0; o[nt][1] *= c0;
            o[nt][2] *= c1; o[nt][3] *= c1;
        }
        __syncwarp();                      // P visible within warp

        // ---- O += P(16x64) x V(64x128) ----
        #pragma unroll
        for (int kk = 0; kk < 64; kk += 8) {
            unsigned pf[4];
            pf[0] = f2tf32(Ps[g * PSTR + kk + t]);
            pf[1] = f2tf32(Ps[(g + 8) * PSTR + kk + t]);
            pf[2] = f2tf32(Ps[g * PSTR + kk + 4 + t]);
            pf[3] = f2tf32(Ps[(g + 8) * PSTR + kk + 4 + t]);
            #pragma unroll
            for (int nt = 0; nt < 16; nt++) {
                unsigned bf[2];
                bf[0] = f2tf32(Vs[(kk + t) * VSTR + nt * 8 + g]);
                bf[1] = f2tf32(Vs[(kk + 4 + t) * VSTR + nt * 8 + g]);
                mma_tf32(o[nt], pf, bf);
            }
        }
        __syncwarp();                      // P reads done before next write
    }

    // ---- normalize + store ----
    float inv0 = 1.f / l0, inv1 = 1.f / l1;
    int r0 = q0 + wrow + g, r1 = q0 + wrow + 8 + g;
    #pragma unroll
    for (int nt = 0; nt < 16; nt++) {
        int d = nt * 8 + 2 * t;
        *(float2*)(Og + base + (size_t)r0 * HID + d) =
            make_float2(o[nt][0] * inv0, o[nt][1] * inv0);
        *(float2*)(Og + base + (size_t)r1 * HID + d) =
            make_float2(o[nt][2] * inv1, o[nt][3] * inv1);
    }
}

// =====================================================================
// launcher
// =====================================================================
extern "C" void kernel_launch(void* const* d_in, const int* in_sizes, int n_in,
                              void* d_out, int out_size)
{
    const float* X   = (const float*)d_in[0];
    const float* qw  = (const float*)d_in[1];
    const float* qb  = (const float*)d_in[2];
    const float* kw  = (const float*)d_in[3];
    const float* kb  = (const float*)d_in[4];
    const float* vw  = (const float*)d_in[5];
    const float* vb  = (const float*)d_in[6];
    const float* ow  = (const float*)d_in[7];
    const float* ob  = (const float*)d_in[8];
    const float* qg  = (const float*)d_in[9];
    const float* qnb = (const float*)d_in[10];
    const float* kg  = (const float*)d_in[11];
    const float* knb = (const float*)d_in[12];
    float* out = (float*)d_out;

    float *Q, *K, *V, *AO;
    cudaGetSymbolAddress((void**)&Q,  g_Q);
    cudaGetSymbolAddress((void**)&K,  g_K);
    cudaGetSymbolAddress((void**)&V,  g_V);
    cudaGetSymbolAddress((void**)&AO, g_AO);

    cudaFuncSetAttribute(flash_attn_tc,
                         cudaFuncAttributeMaxDynamicSharedMemorySize,
                         FLASH_SMEM);

    dim3 gg(HID / 128, NTOK / 128);   // (16, 32)
    dim3 bb(128);
    tf32_gemm_bias<<<gg, bb>>>(X, qw, qb, Q, NTOK, HID, HID);
    tf32_gemm_bias<<<gg, bb>>>(X, kw, kb, K, NTOK, HID, HID);
    tf32_gemm_bias<<<gg, bb>>>(X, vw, vb, V, NTOK, HID, HID);

    qk_ln<<<NTOK, 512>>>(Q, K, qg, qnb, kg, knb);

    flash_attn_tc<<<dim3(2048 / 128, 32), 256, FLASH_SMEM>>>(Q, K, V, AO);

    tf32_gemm_bias<<<gg, bb>>>(AO, ow, ob, out, NTOK, HID, HID);
}

// round 9
// speedup vs baseline: 3.3304x; 1.1075x over previous
#include <cuda_runtime.h>
#include <cstdint>
#include <math.h>

#define HID 2048
#define NTOK 4096
#define HEADS 16
#define HDIM 128

// ---- scratch (static device arrays; no allocations allowed) ----
__device__ float g_Q[NTOK * HID];
__device__ float g_K[NTOK * HID];
__device__ float g_V[NTOK * HID];
__device__ float g_AO[NTOK * HID];

// =====================================================================
// helpers
// =====================================================================
__device__ __forceinline__ unsigned f2tf32(float f) {
    unsigned u;
    asm("cvt.rna.tf32.f32 %0, %1;" : "=r"(u) : "f"(f));
    return u;
}
__device__ __forceinline__ void mma_tf32(float* c, const unsigned* a,
                                         const unsigned* b) {
    asm volatile(
        "mma.sync.aligned.m16n8k8.row.col.f32.tf32.tf32.f32 "
        "{%0,%1,%2,%3}, {%4,%5,%6,%7}, {%8,%9}, {%0,%1,%2,%3};\n"
        : "+f"(c[0]), "+f"(c[1]), "+f"(c[2]), "+f"(c[3])
        : "r"(a[0]), "r"(a[1]), "r"(a[2]), "r"(a[3]),
          "r"(b[0]), "r"(b[1]));
}
__device__ __forceinline__ void cp16(void* smem_dst, const void* g) {
    unsigned saddr = (unsigned)__cvta_generic_to_shared(smem_dst);
    asm volatile("cp.async.cg.shared.global [%0], [%1], 16;\n"
                 :: "r"(saddr), "l"(g));
}
__device__ __forceinline__ void cp_commit() {
    asm volatile("cp.async.commit_group;\n");
}
__device__ __forceinline__ void cp_wait1() {
    asm volatile("cp.async.wait_group 1;\n");
}
__device__ __forceinline__ void cp_wait0() {
    asm volatile("cp.async.wait_group 0;\n");
}

// =====================================================================
// TF32 tensor-core GEMM with bias: C[M,N] = A[M,K] @ B[K,N] + bias[N]
// 128x128x16 block tile, 128 threads (4 warps, 2x2), warp tile 64x64.
// Shared gemm body (inlined into qkv_gemm / tf32_gemm_bias).
// =====================================================================
#define ASTRIDE 20
#define BSTRIDE 136

__device__ __forceinline__
void gemm_body(const float* __restrict__ A, const float* __restrict__ B,
               const float* __restrict__ bias, float* __restrict__ C)
{
    __shared__ float As[2][128 * ASTRIDE];
    __shared__ float Bs[2][16 * BSTRIDE];

    const int tid  = threadIdx.x;
    const int lane = tid & 31;
    const int g    = lane >> 2;       // 0..7
    const int t    = lane & 3;        // 0..3
    const int wid  = tid >> 5;        // 0..3
    const int warpM = wid & 1;        // 2 x 64 rows
    const int warpN = wid >> 1;       // 2 x 64 cols
    const int row0 = blockIdx.y * 128;
    const int col0 = blockIdx.x * 128;

    const int a_r = tid >> 2,  a_k = (tid & 3) * 4;
    const int b_k = tid >> 5,  b_n = (tid & 31) * 4;

    float acc[4][8][4];
    #pragma unroll
    for (int i = 0; i < 4; i++)
        #pragma unroll
        for (int j = 0; j < 8; j++)
            #pragma unroll
            for (int c = 0; c < 4; c++) acc[i][j][c] = 0.f;

    const int nk = HID >> 4;

    {
        const float* ag = A + (size_t)(row0 + a_r) * HID + a_k;
        #pragma unroll
        for (int r = 0; r < 4; r++)
            cp16(&As[0][(a_r + 32 * r) * ASTRIDE + a_k],
                 ag + (size_t)(32 * r) * HID);
        const float* bg = B + (size_t)b_k * HID + col0 + b_n;
        #pragma unroll
        for (int r = 0; r < 4; r++)
            cp16(&Bs[0][(b_k + 4 * r) * BSTRIDE + b_n],
                 bg + (size_t)(4 * r) * HID);
        cp_commit();
    }

    int buf = 0;
    for (int kt = 0; kt < nk; kt++) {
        if (kt + 1 < nk) {
            const float* ag = A + (size_t)(row0 + a_r) * HID + (kt + 1) * 16 + a_k;
            #pragma unroll
            for (int r = 0; r < 4; r++)
                cp16(&As[buf ^ 1][(a_r + 32 * r) * ASTRIDE + a_k],
                     ag + (size_t)(32 * r) * HID);
            const float* bg = B + (size_t)((kt + 1) * 16 + b_k) * HID + col0 + b_n;
            #pragma unroll
            for (int r = 0; r < 4; r++)
                cp16(&Bs[buf ^ 1][(b_k + 4 * r) * BSTRIDE + b_n],
                     bg + (size_t)(4 * r) * HID);
            cp_commit();
            cp_wait1();
        } else {
            cp_wait0();
        }
        __syncthreads();

        const float* as = &As[buf][0];
        const float* bs = &Bs[buf][0];

        #pragma unroll
        for (int kk = 0; kk < 16; kk += 8) {
            unsigned bf[8][2];
            #pragma unroll
            for (int tn = 0; tn < 8; tn++) {
                int n = warpN * 64 + tn * 8 + g;
                bf[tn][0] = f2tf32(bs[(kk +     t) * BSTRIDE + n]);
                bf[tn][1] = f2tf32(bs[(kk + 4 + t) * BSTRIDE + n]);
            }
            unsigned af[4][4];
            #pragma unroll
            for (int tm = 0; tm < 4; tm++) {
                int m = warpM * 64 + tm * 16 + g;
                af[tm][0] = f2tf32(as[m * ASTRIDE + kk + t]);
                af[tm][1] = f2tf32(as[(m + 8) * ASTRIDE + kk + t]);
                af[tm][2] = f2tf32(as[m * ASTRIDE + kk + 4 + t]);
                af[tm][3] = f2tf32(as[(m + 8) * ASTRIDE + kk + 4 + t]);
            }
            #pragma unroll
            for (int tm = 0; tm < 4; tm++)
                #pragma unroll
                for (int tn = 0; tn < 8; tn++)
                    mma_tf32(acc[tm][tn], af[tm], bf[tn]);
        }
        __syncthreads();
        buf ^= 1;
    }

    #pragma unroll
    for (int tm = 0; tm < 4; tm++) {
        int mrow = row0 + warpM * 64 + tm * 16 + g;
        #pragma unroll
        for (int tn = 0; tn < 8; tn++) {
            int ncol = col0 + warpN * 64 + tn * 8 + t * 2;
            float b0 = bias[ncol], b1 = bias[ncol + 1];
            float2 v0 = make_float2(acc[tm][tn][0] + b0, acc[tm][tn][1] + b1);
            float2 v1 = make_float2(acc[tm][tn][2] + b0, acc[tm][tn][3] + b1);
            *(float2*)(C + (size_t)mrow * HID + ncol) = v0;
            *(float2*)(C + (size_t)(mrow + 8) * HID + ncol) = v1;
        }
    }
}

// fused QKV: one launch, gridDim.z = 3 selects weight/bias/output
__global__ __launch_bounds__(128)
void qkv_gemm(const float* __restrict__ A,
              const float* __restrict__ W0, const float* __restrict__ W1,
              const float* __restrict__ W2,
              const float* __restrict__ b0, const float* __restrict__ b1,
              const float* __restrict__ b2,
              float* __restrict__ C0, float* __restrict__ C1,
              float* __restrict__ C2)
{
    const float* W = (blockIdx.z == 0) ? W0 : (blockIdx.z == 1) ? W1 : W2;
    const float* b = (blockIdx.z == 0) ? b0 : (blockIdx.z == 1) ? b1 : b2;
    float*       C = (blockIdx.z == 0) ? C0 : (blockIdx.z == 1) ? C1 : C2;
    gemm_body(A, W, b, C);
}

__global__ __launch_bounds__(128)
void tf32_gemm_bias(const float* __restrict__ A, const float* __restrict__ B,
                    const float* __restrict__ bias, float* __restrict__ C)
{
    gemm_body(A, B, bias, C);
}

// =====================================================================
// Per-head LayerNorm over head_dim=128 for Q and K (in place).
// =====================================================================
__device__ __forceinline__ void ln_head(float* p, const float* g,
                                        const float* be, int lane)
{
    float4 x = *(float4*)(p + lane * 4);
    float s  = x.x + x.y + x.z + x.w;
    float ss = x.x * x.x + x.y * x.y + x.z * x.z + x.w * x.w;
    #pragma unroll
    for (int off = 16; off > 0; off >>= 1) {
        s  += __shfl_xor_sync(0xffffffffu, s,  off);
        ss += __shfl_xor_sync(0xffffffffu, ss, off);
    }
    float mean = s * (1.f / 128.f);
    float var  = ss * (1.f / 128.f) - mean * mean;
    float rstd = rsqrtf(var + 1e-6f);
    float4 gg = *(const float4*)(g  + lane * 4);
    float4 bb = *(const float4*)(be + lane * 4);
    x.x = (x.x - mean) * rstd * gg.x + bb.x;
    x.y = (x.y - mean) * rstd * gg.y + bb.y;
    x.z = (x.z - mean) * rstd * gg.z + bb.z;
    x.w = (x.w - mean) * rstd * gg.w + bb.w;
    *(float4*)(p + lane * 4) = x;
}

__global__ __launch_bounds__(512)
void qk_ln(float* __restrict__ Q, float* __restrict__ K,
           const float* __restrict__ qg, const float* __restrict__ qb,
           const float* __restrict__ kg, const float* __restrict__ kb)
{
    int tk = blockIdx.x;
    int h = threadIdx.x >> 5;
    int lane = threadIdx.x & 31;
    ln_head(Q + (size_t)tk * HID + h * HDIM, qg, qb, lane);
    ln_head(K + (size_t)tk * HID + h * HDIM, kg, kb, lane);
}

// =====================================================================
// Tensor-core flash attention (legacy tf32 mma) — R5-proven body.
// Block = one (b,h) x 128 Q rows. 256 threads = 8 warps; warp w owns
// Q rows w*16..w*16+15 (private online-softmax state, per-warp P smem).
// =====================================================================
#define QSTR 132
#define KSTR 132
#define VSTR 136
#define PSTR 68
#define FLASH_SMEM ((128 * QSTR + 64 * KSTR + 64 * VSTR + 8 * 16 * PSTR) * 4)

__global__ __launch_bounds__(256)
void flash_attn_tc(const float* __restrict__ Qg, const float* __restrict__ Kg,
                   const float* __restrict__ Vg, float* __restrict__ Og)
{
    extern __shared__ float sm[];
    float* Qs = sm;
    float* Ks = Qs + 128 * QSTR;
    float* Vs = Ks + 64 * KSTR;
    float* Pw = Vs + 64 * VSTR;

    const int tid  = threadIdx.x;
    const int lane = tid & 31;
    const int w    = tid >> 5;
    const int g    = lane >> 2;
    const int t    = lane & 3;
    const int bh = blockIdx.y;
    const int b  = bh >> 4, h = bh & 15;
    const int q0 = blockIdx.x * 128;
    const size_t base = (size_t)b * 2048 * HID + (size_t)h * HDIM;
    const float scale = 0.08838834764831845f;

    float* Ps = Pw + w * 16 * PSTR;
    const int wrow = w * 16;

    for (int i = tid; i < 128 * 32; i += 256) {
        int r = i >> 5, c4 = (i & 31) << 2;
        float4 q = *(const float4*)(Qg + base + (size_t)(q0 + r) * HID + c4);
        q.x *= scale; q.y *= scale; q.z *= scale; q.w *= scale;
        *(float4*)(Qs + r * QSTR + c4) = q;
    }

    float m0 = -1e30f, m1 = -1e30f, l0 = 0.f, l1 = 0.f;
    float o[16][4];
    #pragma unroll
    for (int nt = 0; nt < 16; nt++)
        #pragma unroll
        for (int c = 0; c < 4; c++) o[nt][c] = 0.f;

    for (int kt = 0; kt < 2048 / 64; kt++) {
        const int k0 = kt * 64;
        __syncthreads();
        for (int i = tid; i < 64 * 32; i += 256) {
            int r = i >> 5, c4 = (i & 31) << 2;
            *(float4*)(Ks + r * KSTR + c4) =
                *(const float4*)(Kg + base + (size_t)(k0 + r) * HID + c4);
            *(float4*)(Vs + r * VSTR + c4) =
                *(const float4*)(Vg + base + (size_t)(k0 + r) * HID + c4);
        }
        __syncthreads();

        float s[8][4];
        #pragma unroll
        for (int nt = 0; nt < 8; nt++)
            #pragma unroll
            for (int c = 0; c < 4; c++) s[nt][c] = 0.f;

        #pragma unroll
        for (int kk = 0; kk < 128; kk += 8) {
            unsigned af[4];
            af[0] = f2tf32(Qs[(wrow + g) * QSTR + kk + t]);
            af[1] = f2tf32(Qs[(wrow + 8 + g) * QSTR + kk + t]);
            af[2] = f2tf32(Qs[(wrow + g) * QSTR + kk + 4 + t]);
            af[3] = f2tf32(Qs[(wrow + 8 + g) * QSTR + kk + 4 + t]);
            #pragma unroll
            for (int nt = 0; nt < 8; nt++) {
                unsigned bf[2];
                bf[0] = f2tf32(Ks[(nt * 8 + g) * KSTR + kk + t]);
                bf[1] = f2tf32(Ks[(nt * 8 + g) * KSTR + kk + 4 + t]);
                mma_tf32(s[nt], af, bf);
            }
        }

        float mx0 = -1e30f, mx1 = -1e30f;
        #pragma unroll
        for (int nt = 0; nt < 8; nt++) {
            mx0 = fmaxf(mx0, fmaxf(s[nt][0], s[nt][1]));
            mx1 = fmaxf(mx1, fmaxf(s[nt][2], s[nt][3]));
        }
        #pragma unroll
        for (int off = 1; off < 4; off <<= 1) {
            mx0 = fmaxf(mx0, __shfl_xor_sync(0xffffffffu, mx0, off));
            mx1 = fmaxf(mx1, __shfl_xor_sync(0xffffffffu, mx1, off));
        }
        float mn0 = fmaxf(m0, mx0), mn1 = fmaxf(m1, mx1);
        float c0 = __expf(m0 - mn0), c1 = __expf(m1 - mn1);
        m0 = mn0; m1 = mn1;

        float ls0 = 0.f, ls1 = 0.f;
        #pragma unroll
        for (int nt = 0; nt < 8; nt++) {
            float p00 = __expf(s[nt][0] - m0);
            float p01 = __expf(s[nt][1] - m0);
            float p10 = __expf(s[nt][2] - m1);
            float p11 = __expf(s[nt][3] - m1);
            ls0 += p00 + p01;
            ls1 += p10 + p11;
            *(float2*)(Ps + g * PSTR + nt * 8 + 2 * t)       = make_float2(p00, p01);
            *(float2*)(Ps + (g + 8) * PSTR + nt * 8 + 2 * t) = make_float2(p10, p11);
        }
        #pragma unroll
        for (int off = 1; off < 4; off <<= 1) {
            ls0 += __shfl_xor_sync(0xffffffffu, ls0, off);
            ls1 += __shfl_xor_sync(0xffffffffu, ls1, off);
        }
        l0 = l0 * c0 + ls0;
        l1 = l1 * c1 + ls1;
        #pragma unroll
        for (int nt = 0; nt < 16; nt++) {
            o[nt][0] *= c0; o[nt][1] *= c0;
            o[nt][2] *= c1; o[nt][3] *= c1;
        }
        __syncwarp();

        #pragma unroll
        for (int kk = 0; kk < 64; kk += 8) {
            unsigned pf[4];
            pf[0] = f2tf32(Ps[g * PSTR + kk + t]);
            pf[1] = f2tf32(Ps[(g + 8) * PSTR + kk + t]);
            pf[2] = f2tf32(Ps[g * PSTR + kk + 4 + t]);
            pf[3] = f2tf32(Ps[(g + 8) * PSTR + kk + 4 + t]);
            #pragma unroll
            for (int nt = 0; nt < 16; nt++) {
                unsigned bf[2];
                bf[0] = f2tf32(Vs[(kk + t) * VSTR + nt * 8 + g]);
                bf[1] = f2tf32(Vs[(kk + 4 + t) * VSTR + nt * 8 + g]);
                mma_tf32(o[nt], pf, bf);
            }
        }
        __syncwarp();
    }

    float inv0 = 1.f / l0, inv1 = 1.f / l1;
    int r0 = q0 + wrow + g, r1 = q0 + wrow + 8 + g;
    #pragma unroll
    for (int nt = 0; nt < 16; nt++) {
        int d = nt * 8 + 2 * t;
        *(float2*)(Og + base + (size_t)r0 * HID + d) =
            make_float2(o[nt][0] * inv0, o[nt][1] * inv0);
        *(float2*)(Og + base + (size_t)r1 * HID + d) =
            make_float2(o[nt][2] * inv1, o[nt][3] * inv1);
    }
}

// =====================================================================
// launcher
// =====================================================================
extern "C" void kernel_launch(void* const* d_in, const int* in_sizes, int n_in,
                              void* d_out, int out_size)
{
    const float* X   = (const float*)d_in[0];
    const float* qw  = (const float*)d_in[1];
    const float* qb  = (const float*)d_in[2];
    const float* kw  = (const float*)d_in[3];
    const float* kb  = (const float*)d_in[4];
    const float* vw  = (const float*)d_in[5];
    const float* vb  = (const float*)d_in[6];
    const float* ow  = (const float*)d_in[7];
    const float* ob  = (const float*)d_in[8];
    const float* qg  = (const float*)d_in[9];
    const float* qnb = (const float*)d_in[10];
    const float* kg  = (const float*)d_in[11];
    const float* knb = (const float*)d_in[12];
    float* out = (float*)d_out;

    float *Q, *K, *V, *AO;
    cudaGetSymbolAddress((void**)&Q,  g_Q);
    cudaGetSymbolAddress((void**)&K,  g_K);
    cudaGetSymbolAddress((void**)&V,  g_V);
    cudaGetSymbolAddress((void**)&AO, g_AO);

    cudaFuncSetAttribute(flash_attn_tc,
                         cudaFuncAttributeMaxDynamicSharedMemorySize,
                         FLASH_SMEM);

    // fused QKV projection: one launch, z selects q/k/v
    dim3 gq(HID / 128, NTOK / 128, 3);   // (16, 32, 3)
    qkv_gemm<<<gq, 128>>>(X, qw, kw, vw, qb, kb, vb, Q, K, V);

    qk_ln<<<NTOK, 512>>>(Q, K, qg, qnb, kg, knb);

    flash_attn_tc<<<dim3(2048 / 128, 32), 256, FLASH_SMEM>>>(Q, K, V, AO);

    dim3 gg(HID / 128, NTOK / 128);      // (16, 32)
    tf32_gemm_bias<<<gg, 128>>>(AO, ow, ob, out);
}

// round 10
// speedup vs baseline: 3.4764x; 1.0438x over previous
#include <cuda_runtime.h>
#include <cstdint>
#include <math.h>

#define HID 2048
#define NTOK 4096
#define HEADS 16
#define HDIM 128

// ---- scratch (static device arrays; no allocations allowed) ----
__device__ float g_Q[NTOK * HID];
__device__ float g_K[NTOK * HID];
__device__ float g_V[NTOK * HID];
__device__ float g_AO[NTOK * HID];
__device__ float g_Xr[NTOK * HID];        // tf32-rounded hidden_states
__device__ float g_Wr[4][HID * HID];      // tf32-rounded weights (same layout)

// =====================================================================
// helpers
// =====================================================================
__device__ __forceinline__ unsigned f2tf32(float f) {
    unsigned u;
    asm("cvt.rna.tf32.f32 %0, %1;" : "=r"(u) : "f"(f));
    return u;
}
__device__ __forceinline__ void mma_tf32(float* c, const unsigned* a,
                                         const unsigned* b) {
    asm volatile(
        "mma.sync.aligned.m16n8k8.row.col.f32.tf32.tf32.f32 "
        "{%0,%1,%2,%3}, {%4,%5,%6,%7}, {%8,%9}, {%0,%1,%2,%3};\n"
        : "+f"(c[0]), "+f"(c[1]), "+f"(c[2]), "+f"(c[3])
        : "r"(a[0]), "r"(a[1]), "r"(a[2]), "r"(a[3]),
          "r"(b[0]), "r"(b[1]));
}
__device__ __forceinline__ void cp16(void* smem_dst, const void* g) {
    unsigned saddr = (unsigned)__cvta_generic_to_shared(smem_dst);
    asm volatile("cp.async.cg.shared.global [%0], [%1], 16;\n"
                 :: "r"(saddr), "l"(g));
}
__device__ __forceinline__ void cp_commit() {
    asm volatile("cp.async.commit_group;\n");
}
__device__ __forceinline__ void cp_wait1() {
    asm volatile("cp.async.wait_group 1;\n");
}
__device__ __forceinline__ void cp_wait0() {
    asm volatile("cp.async.wait_group 0;\n");
}

// =====================================================================
// prep: round X and the 4 weights to exact tf32 values (rna), in gmem.
// grid = (1024, 5); z=0 -> X (2M float4), z=1..4 -> weights (1M float4).
// =====================================================================
__global__ __launch_bounds__(256)
void round_prep(const float* __restrict__ X,
                const float* __restrict__ w0, const float* __restrict__ w1,
                const float* __restrict__ w2, const float* __restrict__ w3,
                float* __restrict__ Xr,
                float* __restrict__ r0, float* __restrict__ r1,
                float* __restrict__ r2, float* __restrict__ r3)
{
    int z = blockIdx.y;
    const float4* src;
    float4* dst;
    int n4;
    if (z == 0)      { src = (const float4*)X;  dst = (float4*)Xr; n4 = NTOK * HID / 4; }
    else if (z == 1) { src = (const float4*)w0; dst = (float4*)r0; n4 = HID * HID / 4; }
    else if (z == 2) { src = (const float4*)w1; dst = (float4*)r1; n4 = HID * HID / 4; }
    else if (z == 3) { src = (const float4*)w2; dst = (float4*)r2; n4 = HID * HID / 4; }
    else             { src = (const float4*)w3; dst = (float4*)r3; n4 = HID * HID / 4; }

    int i = blockIdx.x * blockDim.x + threadIdx.x;
    int stride = gridDim.x * blockDim.x;
    for (; i < n4; i += stride) {
        float4 v = src[i];
        v.x = __uint_as_float(f2tf32(v.x));
        v.y = __uint_as_float(f2tf32(v.y));
        v.z = __uint_as_float(f2tf32(v.z));
        v.w = __uint_as_float(f2tf32(v.w));
        dst[i] = v;
    }
}

// =====================================================================
// TF32 tensor-core GEMM with bias: C[M,N] = A[M,K] @ B[K,N] + bias[N]
// Inputs are pre-rounded to exact tf32 -> NO cvt in the mainloop.
// 128x128x32 block tile, 128 threads (4 warps, 2x2), warp tile 64x64.
// Dynamic smem, double-buffered cp.async.
// A stride 36 (bank 4g+t distinct), B stride 136 (bank 8t+g distinct).
// =====================================================================
#define ASTR 36
#define BSTR 136
#define GEMM_SMEM ((2 * 128 * ASTR + 2 * 32 * BSTR) * 4)   // 71680 B

__device__ __forceinline__
void gemm_body(const float* __restrict__ A, const float* __restrict__ B,
               const float* __restrict__ bias, float* __restrict__ C)
{
    extern __shared__ float gsm[];
    float* Asm[2] = { gsm, gsm + 128 * ASTR };
    float* Bsm[2] = { gsm + 2 * 128 * ASTR, gsm + 2 * 128 * ASTR + 32 * BSTR };

    const int tid  = threadIdx.x;
    const int lane = tid & 31;
    const int g    = lane >> 2;       // 0..7
    const int t    = lane & 3;        // 0..3
    const int wid  = tid >> 5;        // 0..3
    const int warpM = wid & 1;        // 2 x 64 rows
    const int warpN = wid >> 1;       // 2 x 64 cols
    const int row0 = blockIdx.y * 128;
    const int col0 = blockIdx.x * 128;

    float acc[4][8][4];
    #pragma unroll
    for (int i = 0; i < 4; i++)
        #pragma unroll
        for (int j = 0; j < 8; j++)
            #pragma unroll
            for (int c = 0; c < 4; c++) acc[i][j][c] = 0.f;

    const int nk = HID >> 5;          // 64 K-cols per... 32 per tile -> 64 tiles? 2048/32 = 64

    // tile loaders: A 128x32 floats (1024 float4, 8/thread),
    //               B  32x128 floats (1024 float4, 8/thread)
    #define LOAD_TILE(bufi, kt_) { \
        const float* ag = A + (size_t)row0 * HID + (kt_) * 32; \
        _Pragma("unroll") \
        for (int j = 0; j < 8; j++) { \
            int idx = j * 128 + tid; \
            int r = idx >> 3, c = (idx & 7) * 4; \
            cp16(&Asm[bufi][r * ASTR + c], ag + (size_t)r * HID + c); \
        } \
        const float* bg = B + (size_t)((kt_) * 32) * HID + col0; \
        _Pragma("unroll") \
        for (int j = 0; j < 8; j++) { \
            int idx = j * 128 + tid; \
            int kr = idx >> 5, n = (idx & 31) * 4; \
            cp16(&Bsm[bufi][kr * BSTR + n], bg + (size_t)kr * HID + n); \
        } \
        cp_commit(); }

    LOAD_TILE(0, 0);

    int buf = 0;
    for (int kt = 0; kt < nk; kt++) {
        if (kt + 1 < nk) {
            LOAD_TILE(buf ^ 1, kt + 1);
            cp_wait1();
        } else {
            cp_wait0();
        }
        __syncthreads();

        const unsigned* as = (const unsigned*)Asm[buf];
        const unsigned* bs = (const unsigned*)Bsm[buf];

        #pragma unroll
        for (int kk = 0; kk < 32; kk += 8) {
            unsigned bf[8][2];
            #pragma unroll
            for (int tn = 0; tn < 8; tn++) {
                int n = warpN * 64 + tn * 8 + g;
                bf[tn][0] = bs[(kk +     t) * BSTR + n];
                bf[tn][1] = bs[(kk + 4 + t) * BSTR + n];
            }
            unsigned af[4][4];
            #pragma unroll
            for (int tm = 0; tm < 4; tm++) {
                int m = warpM * 64 + tm * 16 + g;
                af[tm][0] = as[m * ASTR + kk + t];
                af[tm][1] = as[(m + 8) * ASTR + kk + t];
                af[tm][2] = as[m * ASTR + kk + 4 + t];
                af[tm][3] = as[(m + 8) * ASTR + kk + 4 + t];
            }
            #pragma unroll
            for (int tm = 0; tm < 4; tm++)
                #pragma unroll
                for (int tn = 0; tn < 8; tn++)
                    mma_tf32(acc[tm][tn], af[tm], bf[tn]);
        }
        __syncthreads();
        buf ^= 1;
    }
    #undef LOAD_TILE

    #pragma unroll
    for (int tm = 0; tm < 4; tm++) {
        int mrow = row0 + warpM * 64 + tm * 16 + g;
        #pragma unroll
        for (int tn = 0; tn < 8; tn++) {
            int ncol = col0 + warpN * 64 + tn * 8 + t * 2;
            float b0 = bias[ncol], b1 = bias[ncol + 1];
            float2 v0 = make_float2(acc[tm][tn][0] + b0, acc[tm][tn][1] + b1);
            float2 v1 = make_float2(acc[tm][tn][2] + b0, acc[tm][tn][3] + b1);
            *(float2*)(C + (size_t)mrow * HID + ncol) = v0;
            *(float2*)(C + (size_t)(mrow + 8) * HID + ncol) = v1;
        }
    }
}

// fused QKV: one launch, gridDim.z = 3 selects weight/bias/output
__global__ __launch_bounds__(128)
void qkv_gemm(const float* __restrict__ A,
              const float* __restrict__ W0, const float* __restrict__ W1,
              const float* __restrict__ W2,
              const float* __restrict__ b0, const float* __restrict__ b1,
              const float* __restrict__ b2,
              float* __restrict__ C0, float* __restrict__ C1,
              float* __restrict__ C2)
{
    const float* W = (blockIdx.z == 0) ? W0 : (blockIdx.z == 1) ? W1 : W2;
    const float* b = (blockIdx.z == 0) ? b0 : (blockIdx.z == 1) ? b1 : b2;
    float*       C = (blockIdx.z == 0) ? C0 : (blockIdx.z == 1) ? C1 : C2;
    gemm_body(A, W, b, C);
}

__global__ __launch_bounds__(128)
void tf32_gemm_bias(const float* __restrict__ A, const float* __restrict__ B,
                    const float* __restrict__ bias, float* __restrict__ C)
{
    gemm_body(A, B, bias, C);
}

// =====================================================================
// Per-head LayerNorm over head_dim=128 for Q and K (in place).
// =====================================================================
__device__ __forceinline__ void ln_head(float* p, const float* g,
                                        const float* be, int lane)
{
    float4 x = *(float4*)(p + lane * 4);
    float s  = x.x + x.y + x.z + x.w;
    float ss = x.x * x.x + x.y * x.y + x.z * x.z + x.w * x.w;
    #pragma unroll
    for (int off = 16; off > 0; off >>= 1) {
        s  += __shfl_xor_sync(0xffffffffu, s,  off);
        ss += __shfl_xor_sync(0xffffffffu, ss, off);
    }
    float mean = s * (1.f / 128.f);
    float var  = ss * (1.f / 128.f) - mean * mean;
    float rstd = rsqrtf(var + 1e-6f);
    float4 gg = *(const float4*)(g  + lane * 4);
    float4 bb = *(const float4*)(be + lane * 4);
    x.x = (x.x - mean) * rstd * gg.x + bb.x;
    x.y = (x.y - mean) * rstd * gg.y + bb.y;
    x.z = (x.z - mean) * rstd * gg.z + bb.z;
    x.w = (x.w - mean) * rstd * gg.w + bb.w;
    *(float4*)(p + lane * 4) = x;
}

__global__ __launch_bounds__(512)
void qk_ln(float* __restrict__ Q, float* __restrict__ K,
           const float* __restrict__ qg, const float* __restrict__ qb,
           const float* __restrict__ kg, const float* __restrict__ kb)
{
    int tk = blockIdx.x;
    int h = threadIdx.x >> 5;
    int lane = threadIdx.x & 31;
    ln_head(Q + (size_t)tk * HID + h * HDIM, qg, qb, lane);
    ln_head(K + (size_t)tk * HID + h * HDIM, kg, kb, lane);
}

// =====================================================================
// Tensor-core flash attention (legacy tf32 mma) — R5-proven body.
// Epilogue stores AO pre-rounded to tf32 (O-proj consumes directly).
// =====================================================================
#define QSTR 132
#define KSTR 132
#define VSTR 136
#define PSTR 68
#define FLASH_SMEM ((128 * QSTR + 64 * KSTR + 64 * VSTR + 8 * 16 * PSTR) * 4)

__global__ __launch_bounds__(256)
void flash_attn_tc(const float* __restrict__ Qg, const float* __restrict__ Kg,
                   const float* __restrict__ Vg, float* __restrict__ Og)
{
    extern __shared__ float sm[];
    float* Qs = sm;
    float* Ks = Qs + 128 * QSTR;
    float* Vs = Ks + 64 * KSTR;
    float* Pw = Vs + 64 * VSTR;

    const int tid  = threadIdx.x;
    const int lane = tid & 31;
    const int w    = tid >> 5;
    const int g    = lane >> 2;
    const int t    = lane & 3;
    const int bh = blockIdx.y;
    const int b  = bh >> 4, h = bh & 15;
    const int q0 = blockIdx.x * 128;
    const size_t base = (size_t)b * 2048 * HID + (size_t)h * HDIM;
    const float scale = 0.08838834764831845f;

    float* Ps = Pw + w * 16 * PSTR;
    const int wrow = w * 16;

    for (int i = tid; i < 128 * 32; i += 256) {
        int r = i >> 5, c4 = (i & 31) << 2;
        float4 q = *(const float4*)(Qg + base + (size_t)(q0 + r) * HID + c4);
        q.x *= scale; q.y *= scale; q.z *= scale; q.w *= scale;
        *(float4*)(Qs + r * QSTR + c4) = q;
    }

    float m0 = -1e30f, m1 = -1e30f, l0 = 0.f, l1 = 0.f;
    float o[16][4];
    #pragma unroll
    for (int nt = 0; nt < 16; nt++)
        #pragma unroll
        for (int c = 0; c < 4; c++) o[nt][c] = 0.f;

    for (int kt = 0; kt < 2048 / 64; kt++) {
        const int k0 = kt * 64;
        __syncthreads();
        for (int i = tid; i < 64 * 32; i += 256) {
            int r = i >> 5, c4 = (i & 31) << 2;
            *(float4*)(Ks + r * KSTR + c4) =
                *(const float4*)(Kg + base + (size_t)(k0 + r) * HID + c4);
            *(float4*)(Vs + r * VSTR + c4) =
                *(const float4*)(Vg + base + (size_t)(k0 + r) * HID + c4);
        }
        __syncthreads();

        float s[8][4];
        #pragma unroll
        for (int nt = 0; nt < 8; nt++)
            #pragma unroll
            for (int c = 0; c < 4; c++) s[nt][c] = 0.f;

        #pragma unroll
        for (int kk = 0; kk < 128; kk += 8) {
            unsigned af[4];
            af[0] = f2tf32(Qs[(wrow + g) * QSTR + kk + t]);
            af[1] = f2tf32(Qs[(wrow + 8 + g) * QSTR + kk + t]);
            af[2] = f2tf32(Qs[(wrow + g) * QSTR + kk + 4 + t]);
            af[3] = f2tf32(Qs[(wrow + 8 + g) * QSTR + kk + 4 + t]);
            #pragma unroll
            for (int nt = 0; nt < 8; nt++) {
                unsigned bf[2];
                bf[0] = f2tf32(Ks[(nt * 8 + g) * KSTR + kk + t]);
                bf[1] = f2tf32(Ks[(nt * 8 + g) * KSTR + kk + 4 + t]);
                mma_tf32(s[nt], af, bf);
            }
        }

        float mx0 = -1e30f, mx1 = -1e30f;
        #pragma unroll
        for (int nt = 0; nt < 8; nt++) {
            mx0 = fmaxf(mx0, fmaxf(s[nt][0], s[nt][1]));
            mx1 = fmaxf(mx1, fmaxf(s[nt][2], s[nt][3]));
        }
        #pragma unroll
        for (int off = 1; off < 4; off <<= 1) {
            mx0 = fmaxf(mx0, __shfl_xor_sync(0xffffffffu, mx0, off));
            mx1 = fmaxf(mx1, __shfl_xor_sync(0xffffffffu, mx1, off));
        }
        float mn0 = fmaxf(m0, mx0), mn1 = fmaxf(m1, mx1);
        float c0 = __expf(m0 - mn0), c1 = __expf(m1 - mn1);
        m0 = mn0; m1 = mn1;

        float ls0 = 0.f, ls1 = 0.f;
        #pragma unroll
        for (int nt = 0; nt < 8; nt++) {
            float p00 = __expf(s[nt][0] - m0);
            float p01 = __expf(s[nt][1] - m0);
            float p10 = __expf(s[nt][2] - m1);
            float p11 = __expf(s[nt][3] - m1);
            ls0 += p00 + p01;
            ls1 += p10 + p11;
            *(float2*)(Ps + g * PSTR + nt * 8 + 2 * t)       = make_float2(p00, p01);
            *(float2*)(Ps + (g + 8) * PSTR + nt * 8 + 2 * t) = make_float2(p10, p11);
        }
        #pragma unroll
        for (int off = 1; off < 4; off <<= 1) {
            ls0 += __shfl_xor_sync(0xffffffffu, ls0, off);
            ls1 += __shfl_xor_sync(0xffffffffu, ls1, off);
        }
        l0 = l0 * c0 + ls0;
        l1 = l1 * c1 + ls1;
        #pragma unroll
        for (int nt = 0; nt < 16; nt++) {
            o[nt][0] *= c0; o[nt][1] *= c0;
            o[nt][2] *= c1; o[nt][3] *= c1;
        }
        __syncwarp();

        #pragma unroll
        for (int kk = 0; kk < 64; kk += 8) {
            unsigned pf[4];
            pf[0] = f2tf32(Ps[g * PSTR + kk + t]);
            pf[1] = f2tf32(Ps[(g + 8) * PSTR + kk + t]);
            pf[2] = f2tf32(Ps[g * PSTR + kk + 4 + t]);
            pf[3] = f2tf32(Ps[(g + 8) * PSTR + kk + 4 + t]);
            #pragma unroll
            for (int nt = 0; nt < 16; nt++) {
                unsigned bf[2];
                bf[0] = f2tf32(Vs[(kk + t) * VSTR + nt * 8 + g]);
                bf[1] = f2tf32(Vs[(kk + 4 + t) * VSTR + nt * 8 + g]);
                mma_tf32(o[nt], pf, bf);
            }
        }
        __syncwarp();
    }

    // store AO pre-rounded to tf32 (exactly what O-proj's cvt produced in R9)
    float inv0 = 1.f / l0, inv1 = 1.f / l1;
    int r0 = q0 + wrow + g, r1 = q0 + wrow + 8 + g;
    #pragma unroll
    for (int nt = 0; nt < 16; nt++) {
        int d = nt * 8 + 2 * t;
        float2 v0 = make_float2(
            __uint_as_float(f2tf32(o[nt][0] * inv0)),
            __uint_as_float(f2tf32(o[nt][1] * inv0)));
        float2 v1 = make_float2(
            __uint_as_float(f2tf32(o[nt][2] * inv1)),
            __uint_as_float(f2tf32(o[nt][3] * inv1)));
        *(float2*)(Og + base + (size_t)r0 * HID + d) = v0;
        *(float2*)(Og + base + (size_t)r1 * HID + d) = v1;
    }
}

// =====================================================================
// launcher
// =====================================================================
extern "C" void kernel_launch(void* const* d_in, const int* in_sizes, int n_in,
                              void* d_out, int out_size)
{
    const float* X   = (const float*)d_in[0];
    const float* qw  = (const float*)d_in[1];
    const float* qb  = (const float*)d_in[2];
    const float* kw  = (const float*)d_in[3];
    const float* kb  = (const float*)d_in[4];
    const float* vw  = (const float*)d_in[5];
    const float* vb  = (const float*)d_in[6];
    const float* ow  = (const float*)d_in[7];
    const float* ob  = (const float*)d_in[8];
    const float* qg  = (const float*)d_in[9];
    const float* qnb = (const float*)d_in[10];
    const float* kg  = (const float*)d_in[11];
    const float* knb = (const float*)d_in[12];
    float* out = (float*)d_out;

    float *Q, *K, *V, *AO, *Xr, *Wr;
    cudaGetSymbolAddress((void**)&Q,  g_Q);
    cudaGetSymbolAddress((void**)&K,  g_K);
    cudaGetSymbolAddress((void**)&V,  g_V);
    cudaGetSymbolAddress((void**)&AO, g_AO);
    cudaGetSymbolAddress((void**)&Xr, g_Xr);
    cudaGetSymbolAddress((void**)&Wr, g_Wr);
    float* qwr = Wr;
    float* kwr = Wr + (size_t)HID * HID;
    float* vwr = Wr + 2 * (size_t)HID * HID;
    float* owr = Wr + 3 * (size_t)HID * HID;

    cudaFuncSetAttribute(flash_attn_tc,
                         cudaFuncAttributeMaxDynamicSharedMemorySize,
                         FLASH_SMEM);
    cudaFuncSetAttribute(qkv_gemm,
                         cudaFuncAttributeMaxDynamicSharedMemorySize,
                         GEMM_SMEM);
    cudaFuncSetAttribute(tf32_gemm_bias,
                         cudaFuncAttributeMaxDynamicSharedMemorySize,
                         GEMM_SMEM);

    // prep: round X and weights to exact tf32 once
    round_prep<<<dim3(1024, 5), 256>>>(X, qw, kw, vw, ow,
                                       Xr, qwr, kwr, vwr, owr);

    // fused QKV projection: one launch, z selects q/k/v
    dim3 gq(HID / 128, NTOK / 128, 3);   // (16, 32, 3)
    qkv_gemm<<<gq, 128, GEMM_SMEM>>>(Xr, qwr, kwr, vwr, qb, kb, vb, Q, K, V);

    qk_ln<<<NTOK, 512>>>(Q, K, qg, qnb, kg, knb);

    flash_attn_tc<<<dim3(2048 / 128, 32), 256, FLASH_SMEM>>>(Q, K, V, AO);

    dim3 gg(HID / 128, NTOK / 128);      // (16, 32)
    tf32_gemm_bias<<<gg, 128, GEMM_SMEM>>>(AO, owr, ob, out);
}